// round 1
// baseline (speedup 1.0000x reference)
#include <cuda_runtime.h>
#include <cstdint>

// Problem dims (fixed by the reference)
#define S_DIM 4096
#define E_DIM 1024
#define H_DIM 8
#define HE_DIM (H_DIM * E_DIM)   // 8192

// ---------------- scratch (device globals; no allocations allowed) ----------
__device__ float g_Q[H_DIM * S_DIM * E_DIM];   // 128 MB
__device__ float g_K[H_DIM * S_DIM * E_DIM];   // 128 MB
__device__ float g_V[H_DIM * S_DIM * E_DIM];   // 128 MB
__device__ float g_A[H_DIM * E_DIM * E_DIM];   // 32 MB  (scores -> softmax in place)
__device__ float g_Z[S_DIM * HE_DIM];          // 128 MB (concat of heads)
__device__ float g_O[S_DIM * E_DIM];           // 16 MB
__device__ float g_LN1[S_DIM * E_DIM];         // 16 MB
__device__ float g_FN[S_DIM * E_DIM];          // 16 MB

// ---------------- GEMM tile config ------------------------------------------
#define BM 128
#define BN 128
#define BK 16
#define TM 8
#define TN 8
// 256 threads per block: 16x16 thread grid, 8x8 microtile each.

// ============================================================================
// NT: C[m,n] = alpha * sum_k A[m,k]*B[n,k] (+ bias[n])
// A: [M,K] row-major lda, B: [N,K] row-major ldb
// ============================================================================
__device__ __forceinline__ void gemm_nt_body(
    const float* __restrict__ A, int lda,
    const float* __restrict__ B, int ldb,
    const float* __restrict__ bias,
    float* __restrict__ C, int ldc,
    int Kd, float alpha)
{
    __shared__ float As[BK][BM];
    __shared__ float Bs[BK][BN];

    const int tid = threadIdx.x;
    const int tx = tid & 15;       // n direction
    const int ty = tid >> 4;       // m direction
    const int m0 = blockIdx.y * BM;
    const int n0 = blockIdx.x * BN;

    // load indexing: tile is 128 rows x 16 k = 2048 floats = 512 float4; 2 per thread
    const int lr = tid >> 2;            // 0..63 (row), second pass +64
    const int lk = (tid & 3) * 4;       // k offset within BK

    const float* Ab = A + (size_t)m0 * lda;
    const float* Bb = B + (size_t)n0 * ldb;

    float acc[TM][TN] = {};

    for (int k0 = 0; k0 < Kd; k0 += BK) {
#pragma unroll
        for (int p = 0; p < 2; p++) {
            const int r = lr + p * 64;
            float4 va = *(const float4*)(Ab + (size_t)r * lda + k0 + lk);
            As[lk + 0][r] = va.x; As[lk + 1][r] = va.y;
            As[lk + 2][r] = va.z; As[lk + 3][r] = va.w;
            float4 vb = *(const float4*)(Bb + (size_t)r * ldb + k0 + lk);
            Bs[lk + 0][r] = vb.x; Bs[lk + 1][r] = vb.y;
            Bs[lk + 2][r] = vb.z; Bs[lk + 3][r] = vb.w;
        }
        __syncthreads();
#pragma unroll
        for (int kk = 0; kk < BK; kk++) {
            float a[TM], b[TN];
#pragma unroll
            for (int i = 0; i < TM; i += 4) *(float4*)&a[i] = *(const float4*)&As[kk][ty * TM + i];
#pragma unroll
            for (int j = 0; j < TN; j += 4) *(float4*)&b[j] = *(const float4*)&Bs[kk][tx * TN + j];
#pragma unroll
            for (int i = 0; i < TM; i++)
#pragma unroll
                for (int j = 0; j < TN; j++) acc[i][j] += a[i] * b[j];
        }
        __syncthreads();
    }

#pragma unroll
    for (int i = 0; i < TM; i++) {
        const int m = m0 + ty * TM + i;
#pragma unroll
        for (int j = 0; j < TN; j += 4) {
            const int n = n0 + tx * TN + j;
            float4 o;
            o.x = acc[i][j + 0] * alpha;
            o.y = acc[i][j + 1] * alpha;
            o.z = acc[i][j + 2] * alpha;
            o.w = acc[i][j + 3] * alpha;
            if (bias) {
                o.x += bias[n + 0]; o.y += bias[n + 1];
                o.z += bias[n + 2]; o.w += bias[n + 3];
            }
            *(float4*)(C + (size_t)m * ldc + n) = o;
        }
    }
}

// ============================================================================
// TN: C[m,n] = alpha * sum_k A[k,m]*B[k,n]
// A: [K,M] row-major lda, B: [K,N] row-major ldb
// ============================================================================
__device__ __forceinline__ void gemm_tn_body(
    const float* __restrict__ A, int lda,
    const float* __restrict__ B, int ldb,
    float* __restrict__ C, int ldc,
    int Kd, float alpha)
{
    __shared__ float As[BK][BM];
    __shared__ float Bs[BK][BN];

    const int tid = threadIdx.x;
    const int tx = tid & 15;
    const int ty = tid >> 4;
    const int m0 = blockIdx.y * BM;
    const int n0 = blockIdx.x * BN;

    // tile: 16 k-rows x 128 cols; thread: row tid>>5 (0..7, +8), col4 (tid&31)*4
    const int lr = tid >> 5;
    const int lc = (tid & 31) * 4;

    float acc[TM][TN] = {};

    for (int k0 = 0; k0 < Kd; k0 += BK) {
#pragma unroll
        for (int p = 0; p < 2; p++) {
            const int r = lr + p * 8;
            float4 va = *(const float4*)(A + (size_t)(k0 + r) * lda + m0 + lc);
            *(float4*)&As[r][lc] = va;
            float4 vb = *(const float4*)(B + (size_t)(k0 + r) * ldb + n0 + lc);
            *(float4*)&Bs[r][lc] = vb;
        }
        __syncthreads();
#pragma unroll
        for (int kk = 0; kk < BK; kk++) {
            float a[TM], b[TN];
#pragma unroll
            for (int i = 0; i < TM; i += 4) *(float4*)&a[i] = *(const float4*)&As[kk][ty * TM + i];
#pragma unroll
            for (int j = 0; j < TN; j += 4) *(float4*)&b[j] = *(const float4*)&Bs[kk][tx * TN + j];
#pragma unroll
            for (int i = 0; i < TM; i++)
#pragma unroll
                for (int j = 0; j < TN; j++) acc[i][j] += a[i] * b[j];
        }
        __syncthreads();
    }

#pragma unroll
    for (int i = 0; i < TM; i++) {
        const int m = m0 + ty * TM + i;
#pragma unroll
        for (int j = 0; j < TN; j += 4) {
            const int n = n0 + tx * TN + j;
            float4 o;
            o.x = acc[i][j + 0] * alpha;
            o.y = acc[i][j + 1] * alpha;
            o.z = acc[i][j + 2] * alpha;
            o.w = acc[i][j + 3] * alpha;
            *(float4*)(C + (size_t)m * ldc + n) = o;
        }
    }
}

// ============================================================================
// NN: C[m,n] = sum_k A[m,k]*B[k,n]
// A: [M,K] row-major lda, B: [K,N] row-major ldb
// ============================================================================
__device__ __forceinline__ void gemm_nn_body(
    const float* __restrict__ A, int lda,
    const float* __restrict__ B, int ldb,
    float* __restrict__ C, int ldc,
    int Kd)
{
    __shared__ float As[BK][BM];
    __shared__ float Bs[BK][BN];

    const int tid = threadIdx.x;
    const int tx = tid & 15;
    const int ty = tid >> 4;
    const int m0 = blockIdx.y * BM;
    const int n0 = blockIdx.x * BN;

    const int lar = tid >> 2;            // A: row 0..63 (+64), k offset (tid&3)*4
    const int lak = (tid & 3) * 4;
    const int lbr = tid >> 5;            // B: k-row 0..7 (+8), col4 (tid&31)*4
    const int lbc = (tid & 31) * 4;

    const float* Ab = A + (size_t)m0 * lda;

    float acc[TM][TN] = {};

    for (int k0 = 0; k0 < Kd; k0 += BK) {
#pragma unroll
        for (int p = 0; p < 2; p++) {
            const int r = lar + p * 64;
            float4 va = *(const float4*)(Ab + (size_t)r * lda + k0 + lak);
            As[lak + 0][r] = va.x; As[lak + 1][r] = va.y;
            As[lak + 2][r] = va.z; As[lak + 3][r] = va.w;
            const int rb = lbr + p * 8;
            float4 vb = *(const float4*)(B + (size_t)(k0 + rb) * ldb + n0 + lbc);
            *(float4*)&Bs[rb][lbc] = vb;
        }
        __syncthreads();
#pragma unroll
        for (int kk = 0; kk < BK; kk++) {
            float a[TM], b[TN];
#pragma unroll
            for (int i = 0; i < TM; i += 4) *(float4*)&a[i] = *(const float4*)&As[kk][ty * TM + i];
#pragma unroll
            for (int j = 0; j < TN; j += 4) *(float4*)&b[j] = *(const float4*)&Bs[kk][tx * TN + j];
#pragma unroll
            for (int i = 0; i < TM; i++)
#pragma unroll
                for (int j = 0; j < TN; j++) acc[i][j] += a[i] * b[j];
        }
        __syncthreads();
    }

#pragma unroll
    for (int i = 0; i < TM; i++) {
        const int m = m0 + ty * TM + i;
#pragma unroll
        for (int j = 0; j < TN; j += 4) {
            const int n = n0 + tx * TN + j;
            float4 o;
            o.x = acc[i][j + 0];
            o.y = acc[i][j + 1];
            o.z = acc[i][j + 2];
            o.w = acc[i][j + 3];
            *(float4*)(C + (size_t)m * ldc + n) = o;
        }
    }
}

// ---------------- block reductions (256 threads) -----------------------------
__device__ __forceinline__ float blockReduceSum256(float v) {
    __shared__ float sb[8];
#pragma unroll
    for (int o = 16; o > 0; o >>= 1) v += __shfl_xor_sync(0xffffffffu, v, o);
    __syncthreads();
    if ((threadIdx.x & 31) == 0) sb[threadIdx.x >> 5] = v;
    __syncthreads();
    float r = sb[0];
#pragma unroll
    for (int i = 1; i < 8; i++) r += sb[i];
    return r;
}

__device__ __forceinline__ float blockReduceMax256(float v) {
    __shared__ float sb[8];
#pragma unroll
    for (int o = 16; o > 0; o >>= 1) v = fmaxf(v, __shfl_xor_sync(0xffffffffu, v, o));
    __syncthreads();
    if ((threadIdx.x & 31) == 0) sb[threadIdx.x >> 5] = v;
    __syncthreads();
    float r = sb[0];
#pragma unroll
    for (int i = 1; i < 8; i++) r = fmaxf(r, sb[i]);
    return r;
}

// ============================================================================
// Kernels
// ============================================================================

// QKV projections: grid (8, 32, 24). z = which*8 + h
__global__ __launch_bounds__(256, 2)
void k_qkv(const float* __restrict__ x,
           const float* __restrict__ Wq, const float* __restrict__ bq,
           const float* __restrict__ Wk, const float* __restrict__ bk,
           const float* __restrict__ Wv, const float* __restrict__ bv)
{
    const int z = blockIdx.z;
    const int which = z >> 3;
    const int h = z & 7;
    const float* W; const float* bias; float* C;
    if (which == 0)      { W = Wq; bias = bq; C = g_Q; }
    else if (which == 1) { W = Wk; bias = bk; C = g_K; }
    else                 { W = Wv; bias = bv; C = g_V; }
    W    += (size_t)h * E_DIM * E_DIM;
    bias += (size_t)h * E_DIM;
    C    += (size_t)h * S_DIM * E_DIM;
    gemm_nt_body(x, E_DIM, W, E_DIM, bias, C, E_DIM, E_DIM, 1.0f);
}

// scores[h] = (K_h^T @ Q_h) / 32 : grid (8, 8, 8)
__global__ __launch_bounds__(256, 2)
void k_scores()
{
    const int h = blockIdx.z;
    const float* A = g_K + (size_t)h * S_DIM * E_DIM;
    const float* B = g_Q + (size_t)h * S_DIM * E_DIM;
    float* C = g_A + (size_t)h * E_DIM * E_DIM;
    gemm_tn_body(A, E_DIM, B, E_DIM, C, E_DIM, S_DIM, 0.03125f); // 1/sqrt(1024)
}

// softmax over last dim of g_A: grid 8192 rows
__global__ __launch_bounds__(256, 4)
void k_softmax()
{
    float* p = g_A + (size_t)blockIdx.x * E_DIM;
    const int tid = threadIdx.x;
    float v[4];
    float m = -1e30f;
#pragma unroll
    for (int i = 0; i < 4; i++) { v[i] = p[tid + i * 256]; m = fmaxf(m, v[i]); }
    m = blockReduceMax256(m);
    float s = 0.f;
#pragma unroll
    for (int i = 0; i < 4; i++) { v[i] = __expf(v[i] - m); s += v[i]; }
    s = blockReduceSum256(s);
    const float inv = 1.0f / s;
#pragma unroll
    for (int i = 0; i < 4; i++) p[tid + i * 256] = v[i] * inv;
}

// Zh[h] = V_h @ A_h, written directly into concat layout g_Z: grid (8, 32, 8)
__global__ __launch_bounds__(256, 2)
void k_zh()
{
    const int h = blockIdx.z;
    const float* A = g_V + (size_t)h * S_DIM * E_DIM;
    const float* B = g_A + (size_t)h * E_DIM * E_DIM;
    float* C = g_Z + (size_t)h * E_DIM;          // column offset, ldc = HE
    gemm_nn_body(A, E_DIM, B, E_DIM, C, HE_DIM, E_DIM);
}

// O = Z @ Wz^T + bz : grid (8, 32, 1)
__global__ __launch_bounds__(256, 2)
void k_oproj(const float* __restrict__ Wz, const float* __restrict__ bz)
{
    gemm_nt_body(g_Z, HE_DIM, Wz, HE_DIM, bz, g_O, E_DIM, HE_DIM, 1.0f);
}

// LN1 = LN(O)*g1+b1 + x : grid 4096 rows
__global__ __launch_bounds__(256, 4)
void k_ln1(const float* __restrict__ x,
           const float* __restrict__ g, const float* __restrict__ b)
{
    const size_t row = blockIdx.x;
    const int tid = threadIdx.x;
    const float* p = g_O + row * E_DIM;
    float v[4]; float s = 0.f;
#pragma unroll
    for (int i = 0; i < 4; i++) { v[i] = p[tid + i * 256]; s += v[i]; }
    const float mean = blockReduceSum256(s) * (1.0f / E_DIM);
    float q = 0.f;
#pragma unroll
    for (int i = 0; i < 4; i++) { const float d = v[i] - mean; q += d * d; }
    const float var = blockReduceSum256(q) * (1.0f / E_DIM);
    const float rstd = rsqrtf(var + 1e-5f);
#pragma unroll
    for (int i = 0; i < 4; i++) {
        const int idx = tid + i * 256;
        g_LN1[row * E_DIM + idx] =
            (v[i] - mean) * rstd * g[idx] + b[idx] + x[row * E_DIM + idx];
    }
}

// FN = LN1 @ Wf^T + bf : grid (8, 32, 1)
__global__ __launch_bounds__(256, 2)
void k_fn(const float* __restrict__ Wf, const float* __restrict__ bf)
{
    gemm_nt_body(g_LN1, E_DIM, Wf, E_DIM, bf, g_FN, E_DIM, E_DIM, 1.0f);
}

// LN2 = LN(FN)*g2+b2 + LN1 -> out : grid 4096 rows
__global__ __launch_bounds__(256, 4)
void k_ln2(const float* __restrict__ g, const float* __restrict__ b,
           float* __restrict__ out)
{
    const size_t row = blockIdx.x;
    const int tid = threadIdx.x;
    const float* p = g_FN + row * E_DIM;
    float v[4]; float s = 0.f;
#pragma unroll
    for (int i = 0; i < 4; i++) { v[i] = p[tid + i * 256]; s += v[i]; }
    const float mean = blockReduceSum256(s) * (1.0f / E_DIM);
    float q = 0.f;
#pragma unroll
    for (int i = 0; i < 4; i++) { const float d = v[i] - mean; q += d * d; }
    const float var = blockReduceSum256(q) * (1.0f / E_DIM);
    const float rstd = rsqrtf(var + 1e-5f);
#pragma unroll
    for (int i = 0; i < 4; i++) {
        const int idx = tid + i * 256;
        out[row * E_DIM + idx] =
            (v[i] - mean) * rstd * g[idx] + b[idx] + g_LN1[row * E_DIM + idx];
    }
}

// ============================================================================
// Launch
// ============================================================================
extern "C" void kernel_launch(void* const* d_in, const int* in_sizes, int n_in,
                              void* d_out, int out_size)
{
    (void)in_sizes; (void)n_in; (void)out_size;
    const float* x  = (const float*)d_in[0];
    const float* Wq = (const float*)d_in[1];
    const float* bq = (const float*)d_in[2];
    const float* Wk = (const float*)d_in[3];
    const float* bk = (const float*)d_in[4];
    const float* Wv = (const float*)d_in[5];
    const float* bv = (const float*)d_in[6];
    const float* Wz = (const float*)d_in[7];
    const float* bz = (const float*)d_in[8];
    const float* g1 = (const float*)d_in[9];
    const float* b1 = (const float*)d_in[10];
    const float* Wf = (const float*)d_in[11];
    const float* bf = (const float*)d_in[12];
    const float* g2 = (const float*)d_in[13];
    const float* b2 = (const float*)d_in[14];
    float* out = (float*)d_out;

    dim3 blk(256);

    // 1. Q/K/V projections (24 batched NT GEMMs, M=4096 N=1024 K=1024)
    k_qkv<<<dim3(E_DIM / BN, S_DIM / BM, 24), blk>>>(x, Wq, bq, Wk, bk, Wv, bv);
    // 2. scores = K^T Q / sqrt(E)  (8x TN GEMM, M=N=1024 K=4096)
    k_scores<<<dim3(E_DIM / BN, E_DIM / BM, H_DIM), blk>>>();
    // 3. softmax over last dim of [H,E,E]
    k_softmax<<<H_DIM * E_DIM, 256>>>();
    // 4. Zh = V @ A -> concat layout (8x NN GEMM, M=4096 N=1024 K=1024)
    k_zh<<<dim3(E_DIM / BN, S_DIM / BM, H_DIM), blk>>>();
    // 5. O = Z @ Wz^T + bz  (NT, M=4096 N=1024 K=8192)
    k_oproj<<<dim3(E_DIM / BN, S_DIM / BM, 1), blk>>>(Wz, bz);
    // 6. LN1 = LN(O) + x
    k_ln1<<<S_DIM, 256>>>(x, g1, b1);
    // 7. FN = LN1 @ Wf^T + bf (NT, M=4096 N=1024 K=1024)
    k_fn<<<dim3(E_DIM / BN, S_DIM / BM, 1), blk>>>(Wf, bf);
    // 8. LN2 = LN(FN) + LN1 -> out
    k_ln2<<<S_DIM, 256>>>(g2, b2, out);
}

// round 3
// speedup vs baseline: 7.8956x; 7.8956x over previous
#include <cuda_runtime.h>
#include <cstdint>

#define S_DIM 4096
#define E_DIM 1024
#define H_DIM 8
#define HE_DIM 8192

// ---------------- scratch (device globals; no allocations) ------------------
__device__ float g_xT [(size_t)E_DIM * S_DIM];           // x^T [E,S] 16MB
__device__ float g_u  [E_DIM];                            // col sums of x
__device__ float g_G4 [(size_t)4 * E_DIM * E_DIM];        // split-K partials 16MB
__device__ float g_G  [(size_t)E_DIM * E_DIM];            // Gram 4MB
__device__ float g_T  [(size_t)H_DIM * E_DIM * E_DIM];    // Wk@G 32MB
__device__ float g_A  [(size_t)H_DIM * E_DIM * E_DIM];    // scores -> softmax 32MB
__device__ float g_AT [(size_t)H_DIM * E_DIM * E_DIM];    // A^T 32MB
__device__ float g_WvT[(size_t)H_DIM * E_DIM * E_DIM];    // Wv^T 32MB
__device__ float g_M  [(size_t)H_DIM * E_DIM * E_DIM];    // Wv^T A 32MB
__device__ float g_PT8[(size_t)H_DIM * E_DIM * E_DIM];    // per-head P^T 32MB
__device__ float g_PT [(size_t)E_DIM * E_DIM];            // P^T 4MB
__device__ float g_qbar[H_DIM * E_DIM];
__device__ float g_kbar[H_DIM * E_DIM];
__device__ float g_r  [H_DIM * E_DIM];
__device__ float g_c  [E_DIM];
__device__ float g_O  [(size_t)S_DIM * E_DIM];
__device__ float g_LN1[(size_t)S_DIM * E_DIM];
__device__ float g_FN [(size_t)S_DIM * E_DIM];

// ============================================================================
// bf16 hi/lo split mma.sync GEMM (NT): C[m,n] = sum_k A[m,k]*B[n,k] (+bn[n])
// CTA 128x128, BK=32 fp32, 256 threads (8 warps, 2x4), warp tile 64x32.
// ============================================================================
#define SROWB 80                 // smem row stride bytes (32 bf16 = 64B, pad 80)
#define TILEB (128 * SROWB)      // 10240 per operand tile
#define STAGEB (4 * TILEB)       // Ahi, Alo, Bhi, Blo
#define SMEMB (2 * STAGEB)       // 81920 double-buffered

struct GemmP {
    const float* A; long long As; int lda;
    const float* B; long long Bs; int ldb;
    float*       C; long long Cs; int ldc;
    const float* bn;
    int K;
};

static __device__ __forceinline__ uint32_t s2u(const void* p) {
    uint32_t a;
    asm("{ .reg .u64 t; cvta.to.shared.u64 t, %1; cvt.u32.u64 %0, t; }"
        : "=r"(a) : "l"(p));
    return a;
}

// pack (lo-k elem a, hi-k elem b) into bf16x2 hi word + residual lo word
static __device__ __forceinline__ void split2(float a, float b,
                                              uint32_t& hi, uint32_t& lo) {
    uint32_t h;
    asm("cvt.rn.bf16x2.f32 %0, %1, %2;" : "=r"(h) : "f"(b), "f"(a));
    float ra = a - __uint_as_float(h << 16);
    float rb = b - __uint_as_float(h & 0xFFFF0000u);
    asm("cvt.rn.bf16x2.f32 %0, %1, %2;" : "=r"(lo) : "f"(rb), "f"(ra));
    hi = h;
}

static __device__ __forceinline__ void gload(float4* rA, float4* rB,
                                             const float* __restrict__ Ab,
                                             const float* __restrict__ Bb,
                                             int lda, int ldb, int k0, int tid) {
#pragma unroll
    for (int i = 0; i < 4; i++) {
        int idx = tid + i * 256;
        int row = idx >> 3;
        int k4 = (idx & 7) * 4;
        rA[i] = *(const float4*)(Ab + (size_t)row * lda + k0 + k4);
        rB[i] = *(const float4*)(Bb + (size_t)row * ldb + k0 + k4);
    }
}

static __device__ __forceinline__ void stage_fill(uint32_t stage,
                                                  const float4* rA,
                                                  const float4* rB, int tid) {
#pragma unroll
    for (int i = 0; i < 4; i++) {
        int idx = tid + i * 256;
        int row = idx >> 3;
        int kb = (idx & 7) * 8;
        uint32_t h0, l0, h1, l1;
        uint32_t aaddr = stage + row * SROWB + kb;
        split2(rA[i].x, rA[i].y, h0, l0);
        split2(rA[i].z, rA[i].w, h1, l1);
        asm volatile("st.shared.v2.u32 [%0], {%1,%2};" :: "r"(aaddr), "r"(h0), "r"(h1));
        asm volatile("st.shared.v2.u32 [%0], {%1,%2};" :: "r"(aaddr + TILEB), "r"(l0), "r"(l1));
        uint32_t baddr = stage + 2 * TILEB + row * SROWB + kb;
        split2(rB[i].x, rB[i].y, h0, l0);
        split2(rB[i].z, rB[i].w, h1, l1);
        asm volatile("st.shared.v2.u32 [%0], {%1,%2};" :: "r"(baddr), "r"(h0), "r"(h1));
        asm volatile("st.shared.v2.u32 [%0], {%1,%2};" :: "r"(baddr + TILEB), "r"(l0), "r"(l1));
    }
}

static __device__ __forceinline__ void ldsm4(uint32_t* r, uint32_t addr) {
    asm volatile("ldmatrix.sync.aligned.m8n8.x4.shared.b16 {%0,%1,%2,%3}, [%4];"
                 : "=r"(r[0]), "=r"(r[1]), "=r"(r[2]), "=r"(r[3]) : "r"(addr));
}
static __device__ __forceinline__ void mma16816(float* d, const uint32_t* a,
                                                const uint32_t* b) {
    asm volatile(
        "mma.sync.aligned.m16n8k16.row.col.f32.bf16.bf16.f32 "
        "{%0,%1,%2,%3},{%4,%5,%6,%7},{%8,%9},{%0,%1,%2,%3};"
        : "+f"(d[0]), "+f"(d[1]), "+f"(d[2]), "+f"(d[3])
        : "r"(a[0]), "r"(a[1]), "r"(a[2]), "r"(a[3]), "r"(b[0]), "r"(b[1]));
}

__global__ __launch_bounds__(256, 1) void k_gemm(GemmP p) {
    extern __shared__ char smem[];
    const int tid = threadIdx.x;
    const int w = tid >> 5, l = tid & 31;
    const int wm = (w >> 2) * 64, wn = (w & 3) * 32;
    const int m0 = blockIdx.y * 128, n0 = blockIdx.x * 128;
    const int z = blockIdx.z;
    const float* Ab = p.A + (size_t)z * p.As + (size_t)m0 * p.lda;
    const float* Bb = p.B + (size_t)z * p.Bs + (size_t)n0 * p.ldb;
    const uint32_t s0 = s2u(smem);

    // ldmatrix per-lane offsets within a stage
    const uint32_t aoff = (uint32_t)((wm + (l & 15)) * SROWB + (l >> 4) * 16);
    const uint32_t boff = (uint32_t)(2 * TILEB +
        (wn + (l & 7) + ((l >> 4) & 1) * 8) * SROWB + ((l >> 3) & 1) * 16);

    float acc[4][4][4];
#pragma unroll
    for (int t = 0; t < 4; t++)
#pragma unroll
        for (int j = 0; j < 4; j++)
#pragma unroll
            for (int r = 0; r < 4; r++) acc[t][j][r] = 0.f;

    const int NC = p.K >> 5;
    float4 rA[4], rB[4];
    gload(rA, rB, Ab, Bb, p.lda, p.ldb, 0, tid);
    stage_fill(s0, rA, rB, tid);
    if (NC > 1) gload(rA, rB, Ab, Bb, p.lda, p.ldb, 32, tid);

    for (int c = 0; c < NC; c++) {
        __syncthreads();
        uint32_t st = s0 + (uint32_t)(c & 1) * STAGEB;
        if (c + 1 < NC) {
            stage_fill(s0 + (uint32_t)((c + 1) & 1) * STAGEB, rA, rB, tid);
            if (c + 2 < NC) gload(rA, rB, Ab, Bb, p.lda, p.ldb, (c + 2) * 32, tid);
        }
#pragma unroll
        for (int ks = 0; ks < 2; ks++) {
            uint32_t ah[4][4], al[4][4], bh[2][4], bl[2][4];
#pragma unroll
            for (int t = 0; t < 4; t++) {
                uint32_t ad = st + aoff + t * (16 * SROWB) + ks * 32;
                ldsm4(ah[t], ad);
                ldsm4(al[t], ad + TILEB);
            }
#pragma unroll
            for (int jp = 0; jp < 2; jp++) {
                uint32_t bd = st + boff + jp * (16 * SROWB) + ks * 32;
                ldsm4(bh[jp], bd);
                ldsm4(bl[jp], bd + TILEB);
            }
#pragma unroll
            for (int t = 0; t < 4; t++) {
#pragma unroll
                for (int j = 0; j < 4; j++) {
                    uint32_t b0h[2] = { bh[j >> 1][(j & 1) * 2], bh[j >> 1][(j & 1) * 2 + 1] };
                    uint32_t b0l[2] = { bl[j >> 1][(j & 1) * 2], bl[j >> 1][(j & 1) * 2 + 1] };
                    mma16816(acc[t][j], ah[t], b0h);
                    mma16816(acc[t][j], ah[t], b0l);
                    mma16816(acc[t][j], al[t], b0h);
                }
            }
        }
    }

    const float* bn = p.bn;
    float* Cb = p.C + (size_t)z * p.Cs;
#pragma unroll
    for (int t = 0; t < 4; t++) {
        int m = m0 + wm + t * 16 + (l >> 2);
#pragma unroll
        for (int j = 0; j < 4; j++) {
            int n = n0 + wn + j * 8 + (l & 3) * 2;
            float2 v0 = make_float2(acc[t][j][0], acc[t][j][1]);
            float2 v1 = make_float2(acc[t][j][2], acc[t][j][3]);
            if (bn) {
                float2 bb = *(const float2*)(bn + n);
                v0.x += bb.x; v0.y += bb.y; v1.x += bb.x; v1.y += bb.y;
            }
            *(float2*)(Cb + (size_t)m * p.ldc + n) = v0;
            *(float2*)(Cb + (size_t)(m + 8) * p.ldc + n) = v1;
        }
    }
}

// ---------------- reductions -------------------------------------------------
static __device__ __forceinline__ float blockReduceSum256(float v) {
    __shared__ float sb[8];
#pragma unroll
    for (int o = 16; o > 0; o >>= 1) v += __shfl_xor_sync(0xffffffffu, v, o);
    __syncthreads();
    if ((threadIdx.x & 31) == 0) sb[threadIdx.x >> 5] = v;
    __syncthreads();
    float r = sb[0];
#pragma unroll
    for (int i = 1; i < 8; i++) r += sb[i];
    return r;
}
static __device__ __forceinline__ float blockReduceMax256(float v) {
    __shared__ float sb[8];
#pragma unroll
    for (int o = 16; o > 0; o >>= 1) v = fmaxf(v, __shfl_xor_sync(0xffffffffu, v, o));
    __syncthreads();
    if ((threadIdx.x & 31) == 0) sb[threadIdx.x >> 5] = v;
    __syncthreads();
    float r = sb[0];
#pragma unroll
    for (int i = 1; i < 8; i++) r = fmaxf(r, sb[i]);
    return r;
}

// ---------------- small kernels ----------------------------------------------
__global__ void k_trans(const float* __restrict__ src, float* __restrict__ dst,
                        int R, int C, long long ss, long long ds) {
    __shared__ float t[32][33];
    src += (size_t)blockIdx.z * ss;
    dst += (size_t)blockIdx.z * ds;
    int c0 = blockIdx.x * 32, r0 = blockIdx.y * 32;
#pragma unroll
    for (int i = 0; i < 32; i += 8)
        t[threadIdx.y + i][threadIdx.x] =
            src[(size_t)(r0 + threadIdx.y + i) * C + c0 + threadIdx.x];
    __syncthreads();
#pragma unroll
    for (int i = 0; i < 32; i += 8)
        dst[(size_t)(c0 + threadIdx.y + i) * R + r0 + threadIdx.x] =
            t[threadIdx.x][threadIdx.y + i];
}

__global__ void k_usum() {   // u[e] = sum_s x[s,e] from xT rows
    int e = blockIdx.x;
    const float* row = g_xT + (size_t)e * S_DIM;
    float s = 0;
    for (int i = threadIdx.x; i < S_DIM; i += 256) s += row[i];
    s = blockReduceSum256(s);
    if (threadIdx.x == 0) g_u[e] = s;
}

__global__ void k_qkbar(const float* __restrict__ Wq, const float* __restrict__ Wk) {
    int f = blockIdx.x, h = blockIdx.y;
    const float* Wrow = (blockIdx.z == 0 ? Wq : Wk) + ((size_t)h * E_DIM + f) * E_DIM;
    float s = 0;
    for (int i = threadIdx.x; i < E_DIM; i += 256) s += g_u[i] * Wrow[i];
    s = blockReduceSum256(s);
    if (threadIdx.x == 0) (blockIdx.z == 0 ? g_qbar : g_kbar)[h * E_DIM + f] = s;
}

// fused rank-1 bias fixup + 1/sqrt(E) scale + softmax (rows of g_A, in place)
__global__ __launch_bounds__(256, 4) void k_softfix(const float* __restrict__ bq,
                                                    const float* __restrict__ bk) {
    int row = blockIdx.x, h = row >> 10, e = row & 1023;
    float* p = g_A + (size_t)row * E_DIM;
    const float bke = bk[h * E_DIM + e], kbe = g_kbar[h * E_DIM + e];
    const float* qb = g_qbar + h * E_DIM;
    const float* bqh = bq + h * E_DIM;
    int tid = threadIdx.x;
    float v[4];
    float m = -1e30f;
#pragma unroll
    for (int i = 0; i < 4; i++) {
        int f = tid + i * 256;
        float s = p[f] + bke * (qb[f] + 4096.0f * bqh[f]) + kbe * bqh[f];
        v[i] = s * 0.03125f;
        m = fmaxf(m, v[i]);
    }
    m = blockReduceMax256(m);
    float sum = 0;
#pragma unroll
    for (int i = 0; i < 4; i++) { v[i] = __expf(v[i] - m); sum += v[i]; }
    sum = blockReduceSum256(sum);
    float inv = 1.0f / sum;
#pragma unroll
    for (int i = 0; i < 4; i++) p[tid + i * 256] = v[i] * inv;
}

__global__ void k_rvec(const float* __restrict__ bv) {  // r[h,f] = sum_e bv[h,e]A[h,e,f]
    int h = blockIdx.y;
    int f = blockIdx.x * 256 + threadIdx.x;
    const float* Ah = g_A + (size_t)h * E_DIM * E_DIM;
    const float* bvh = bv + h * E_DIM;
    float s = 0;
    for (int e = 0; e < E_DIM; e++) s += bvh[e] * Ah[(size_t)e * E_DIM + f];
    g_r[h * E_DIM + f] = s;
}

__global__ void k_cvec(const float* __restrict__ Wz, const float* __restrict__ bz) {
    int o = blockIdx.x;
    const float* wrow = Wz + (size_t)o * HE_DIM;
    float s = 0;
    for (int i = threadIdx.x; i < HE_DIM; i += 256) s += g_r[i] * wrow[i];
    s = blockReduceSum256(s);
    if (threadIdx.x == 0) g_c[o] = bz[o] + s;
}

__global__ void k_reduce(const float* __restrict__ src, float* __restrict__ dst,
                         int Z, int total) {
    int i = blockIdx.x * 256 + threadIdx.x;
    if (i < total) {
        float s = 0;
        for (int zz = 0; zz < Z; zz++) s += src[(size_t)zz * total + i];
        dst[i] = s;
    }
}

__global__ __launch_bounds__(256, 4)
void k_ln1(const float* __restrict__ x, const float* __restrict__ g,
           const float* __restrict__ b) {
    const size_t row = blockIdx.x;
    const int tid = threadIdx.x;
    const float* p = g_O + row * E_DIM;
    float v[4];
    float s = 0.f;
#pragma unroll
    for (int i = 0; i < 4; i++) { v[i] = p[tid + i * 256]; s += v[i]; }
    const float mean = blockReduceSum256(s) * (1.0f / E_DIM);
    float q = 0.f;
#pragma unroll
    for (int i = 0; i < 4; i++) { const float d = v[i] - mean; q += d * d; }
    const float var = blockReduceSum256(q) * (1.0f / E_DIM);
    const float rstd = rsqrtf(var + 1e-5f);
#pragma unroll
    for (int i = 0; i < 4; i++) {
        const int idx = tid + i * 256;
        g_LN1[row * E_DIM + idx] =
            (v[i] - mean) * rstd * g[idx] + b[idx] + x[row * E_DIM + idx];
    }
}

__global__ __launch_bounds__(256, 4)
void k_ln2(const float* __restrict__ g, const float* __restrict__ b,
           float* __restrict__ out) {
    const size_t row = blockIdx.x;
    const int tid = threadIdx.x;
    const float* p = g_FN + row * E_DIM;
    float v[4];
    float s = 0.f;
#pragma unroll
    for (int i = 0; i < 4; i++) { v[i] = p[tid + i * 256]; s += v[i]; }
    const float mean = blockReduceSum256(s) * (1.0f / E_DIM);
    float q = 0.f;
#pragma unroll
    for (int i = 0; i < 4; i++) { const float d = v[i] - mean; q += d * d; }
    const float var = blockReduceSum256(q) * (1.0f / E_DIM);
    const float rstd = rsqrtf(var + 1e-5f);
#pragma unroll
    for (int i = 0; i < 4; i++) {
        const int idx = tid + i * 256;
        out[row * E_DIM + idx] =
            (v[i] - mean) * rstd * g[idx] + b[idx] + g_LN1[row * E_DIM + idx];
    }
}

// ============================================================================
// Launch
// ============================================================================
extern "C" void kernel_launch(void* const* d_in, const int* in_sizes, int n_in,
                              void* d_out, int out_size) {
    (void)in_sizes; (void)n_in; (void)out_size;
    const float* x  = (const float*)d_in[0];
    const float* Wq = (const float*)d_in[1];
    const float* bq = (const float*)d_in[2];
    const float* Wk = (const float*)d_in[3];
    const float* bk = (const float*)d_in[4];
    const float* Wv = (const float*)d_in[5];
    const float* bv = (const float*)d_in[6];
    const float* Wz = (const float*)d_in[7];
    const float* bz = (const float*)d_in[8];
    const float* g1 = (const float*)d_in[9];
    const float* b1 = (const float*)d_in[10];
    const float* Wf = (const float*)d_in[11];
    const float* bf = (const float*)d_in[12];
    const float* g2 = (const float*)d_in[13];
    const float* b2 = (const float*)d_in[14];
    float* out = (float*)d_out;

    static bool attr_set = false;
    if (!attr_set) {
        cudaFuncSetAttribute(k_gemm, cudaFuncAttributeMaxDynamicSharedMemorySize, SMEMB);
        attr_set = true;
    }

    float *dxT, *dG4, *dG, *dT, *dA, *dAT, *dWvT, *dM, *dPT8, *dPT, *dO, *dLN1, *dFN, *dc;
    cudaGetSymbolAddress((void**)&dxT, g_xT);
    cudaGetSymbolAddress((void**)&dG4, g_G4);
    cudaGetSymbolAddress((void**)&dG,  g_G);
    cudaGetSymbolAddress((void**)&dT,  g_T);
    cudaGetSymbolAddress((void**)&dA,  g_A);
    cudaGetSymbolAddress((void**)&dAT, g_AT);
    cudaGetSymbolAddress((void**)&dWvT,g_WvT);
    cudaGetSymbolAddress((void**)&dM,  g_M);
    cudaGetSymbolAddress((void**)&dPT8,g_PT8);
    cudaGetSymbolAddress((void**)&dPT, g_PT);
    cudaGetSymbolAddress((void**)&dO,  g_O);
    cudaGetSymbolAddress((void**)&dLN1,g_LN1);
    cudaGetSymbolAddress((void**)&dFN, g_FN);
    cudaGetSymbolAddress((void**)&dc,  g_c);

    const long long MM = (long long)E_DIM * E_DIM;   // 1M
    dim3 tb(32, 8);

    // x^T, u, Wv^T
    k_trans<<<dim3(E_DIM / 32, S_DIM / 32, 1), tb>>>(x, dxT, S_DIM, E_DIM, 0, 0);
    k_usum<<<E_DIM, 256>>>();
    k_trans<<<dim3(32, 32, H_DIM), tb>>>(Wv, dWvT, E_DIM, E_DIM, MM, MM);

    // G = x^T x via split-K4
    { GemmP p{dxT, 1024, S_DIM, dxT, 1024, S_DIM, dG4, MM, E_DIM, nullptr, 1024};
      k_gemm<<<dim3(8, 8, 4), 256, SMEMB>>>(p); }
    k_reduce<<<(int)(MM / 256), 256>>>(dG4, dG, 4, (int)MM);

    // T_h = Wk_h @ G  (G symmetric -> NT)
    { GemmP p{Wk, MM, E_DIM, dG, 0, E_DIM, dT, MM, E_DIM, nullptr, E_DIM};
      k_gemm<<<dim3(8, 8, H_DIM), 256, SMEMB>>>(p); }
    // scores_h = T_h @ Wq_h^T (raw)
    { GemmP p{dT, MM, E_DIM, Wq, MM, E_DIM, dA, MM, E_DIM, nullptr, E_DIM};
      k_gemm<<<dim3(8, 8, H_DIM), 256, SMEMB>>>(p); }

    // rank-1 bias vectors + fused bias/scale/softmax
    k_qkbar<<<dim3(E_DIM, H_DIM, 2), 256>>>(Wq, Wk);
    k_softfix<<<H_DIM * E_DIM, 256>>>(bq, bk);

    // Z-path bias constants
    k_rvec<<<dim3(4, H_DIM), 256>>>(bv);
    k_cvec<<<E_DIM, 256>>>(Wz, bz);

    // A^T, M_h = Wv_h^T @ A_h, PT_h = Wz_h @ M_h^T-free NT, reduce
    k_trans<<<dim3(32, 32, H_DIM), tb>>>(dA, dAT, E_DIM, E_DIM, MM, MM);
    { GemmP p{dWvT, MM, E_DIM, dAT, MM, E_DIM, dM, MM, E_DIM, nullptr, E_DIM};
      k_gemm<<<dim3(8, 8, H_DIM), 256, SMEMB>>>(p); }
    { GemmP p{Wz, 1024, HE_DIM, dM, MM, E_DIM, dPT8, MM, E_DIM, nullptr, E_DIM};
      k_gemm<<<dim3(8, 8, H_DIM), 256, SMEMB>>>(p); }
    k_reduce<<<(int)(MM / 256), 256>>>(dPT8, dPT, 8, (int)MM);

    // O = x @ P + c
    { GemmP p{x, 0, E_DIM, dPT, 0, E_DIM, dO, 0, E_DIM, dc, E_DIM};
      k_gemm<<<dim3(8, 32, 1), 256, SMEMB>>>(p); }
    k_ln1<<<S_DIM, 256>>>(x, g1, b1);

    // FN = LN1 @ Wf^T + bf
    { GemmP p{dLN1, 0, E_DIM, Wf, 0, E_DIM, dFN, 0, E_DIM, bf, E_DIM};
      k_gemm<<<dim3(8, 32, 1), 256, SMEMB>>>(p); }
    k_ln2<<<S_DIM, 256>>>(g2, b2, out);
}

// round 4
// speedup vs baseline: 9.6754x; 1.2254x over previous
#include <cuda_runtime.h>
#include <cuda_bf16.h>
#include <cstdint>

#define S_DIM 4096
#define E_DIM 1024
#define H_DIM 8
#define HE_DIM 8192
typedef __nv_bfloat16 bf16;

// ---------------- fp32 scratch ----------------------------------------------
__device__ float g_A  [(size_t)H_DIM * E_DIM * E_DIM];  // scores->softmax 32MB
__device__ float g_G4 [(size_t)4 * E_DIM * E_DIM];      // split-K partials
__device__ float g_PT8[(size_t)H_DIM * E_DIM * E_DIM];  // per-head P^T partials
__device__ float g_O  [(size_t)S_DIM * E_DIM];
__device__ float g_LN1[(size_t)S_DIM * E_DIM];
__device__ float g_FN [(size_t)S_DIM * E_DIM];
__device__ float g_u32p[32 * E_DIM];
__device__ float g_u  [E_DIM];
__device__ float g_qbar[H_DIM * E_DIM];
__device__ float g_kbar[H_DIM * E_DIM];
__device__ float g_r8 [8 * H_DIM * E_DIM];
__device__ float g_r  [H_DIM * E_DIM];
__device__ float g_c  [E_DIM];

// ---------------- bf16 hi/lo operand buffers ---------------------------------
__device__ bf16 b_xh [(size_t)S_DIM * E_DIM],  b_xl [(size_t)S_DIM * E_DIM];
__device__ bf16 b_xTh[(size_t)E_DIM * S_DIM],  b_xTl[(size_t)E_DIM * S_DIM];
__device__ bf16 b_Gh [(size_t)E_DIM * E_DIM],  b_Gl [(size_t)E_DIM * E_DIM];
__device__ bf16 b_Wkh[(size_t)H_DIM * E_DIM * E_DIM], b_Wkl[(size_t)H_DIM * E_DIM * E_DIM];
__device__ bf16 b_Wqh[(size_t)H_DIM * E_DIM * E_DIM], b_Wql[(size_t)H_DIM * E_DIM * E_DIM];
__device__ bf16 b_Th [(size_t)H_DIM * E_DIM * E_DIM], b_Tl [(size_t)H_DIM * E_DIM * E_DIM];
__device__ bf16 b_ATh[(size_t)H_DIM * E_DIM * E_DIM], b_ATl[(size_t)H_DIM * E_DIM * E_DIM];
__device__ bf16 b_WvTh[(size_t)H_DIM * E_DIM * E_DIM], b_WvTl[(size_t)H_DIM * E_DIM * E_DIM];
__device__ bf16 b_Mh [(size_t)H_DIM * E_DIM * E_DIM], b_Ml [(size_t)H_DIM * E_DIM * E_DIM];
__device__ bf16 b_Wzh[(size_t)H_DIM * E_DIM * E_DIM], b_Wzl[(size_t)H_DIM * E_DIM * E_DIM];
__device__ bf16 b_PTh[(size_t)E_DIM * E_DIM],  b_PTl[(size_t)E_DIM * E_DIM];
__device__ bf16 b_L1h[(size_t)S_DIM * E_DIM],  b_L1l[(size_t)S_DIM * E_DIM];
__device__ bf16 b_Wfh[(size_t)E_DIM * E_DIM],  b_Wfl[(size_t)E_DIM * E_DIM];

// ---------------- helpers ----------------------------------------------------
static __device__ __forceinline__ uint32_t s2u(const void* p) {
    uint32_t a;
    asm("{ .reg .u64 t; cvta.to.shared.u64 t, %1; cvt.u32.u64 %0, t; }"
        : "=r"(a) : "l"(p));
    return a;
}
static __device__ __forceinline__ uint32_t pack_bf(float a, float b) {
    uint32_t r;
    asm("cvt.rn.bf16x2.f32 %0, %1, %2;" : "=r"(r) : "f"(b), "f"(a));
    return r;
}
static __device__ __forceinline__ void ldsm4(uint32_t* r, uint32_t addr) {
    asm volatile("ldmatrix.sync.aligned.m8n8.x4.shared.b16 {%0,%1,%2,%3}, [%4];"
                 : "=r"(r[0]), "=r"(r[1]), "=r"(r[2]), "=r"(r[3]) : "r"(addr));
}
static __device__ __forceinline__ void mma16816(float* d, const uint32_t* a,
                                                const uint32_t* b) {
    asm volatile(
        "mma.sync.aligned.m16n8k16.row.col.f32.bf16.bf16.f32 "
        "{%0,%1,%2,%3},{%4,%5,%6,%7},{%8,%9},{%0,%1,%2,%3};"
        : "+f"(d[0]), "+f"(d[1]), "+f"(d[2]), "+f"(d[3])
        : "r"(a[0]), "r"(a[1]), "r"(a[2]), "r"(a[3]), "r"(b[0]), "r"(b[1]));
}
static __device__ __forceinline__ void cp16(uint32_t dst, const void* src) {
    asm volatile("cp.async.cg.shared.global [%0], [%1], 16;"
                 :: "r"(dst), "l"(src));
}

// ============================================================================
// bf16 hi/lo cp.async GEMM (NT): C[m,n] = sum_k A[m,k]*B[n,k] (+bn[n])
// CTA 128x128, BK=32, 256 threads (8 warps 2x4, warp tile 64x32), 3 stages.
// Smem row = [hi 32 bf16 (64B) | lo 32 bf16 (64B)] = 128B, XOR-swizzled chunks.
// ============================================================================
#define STAGEB 32768
#define SMEMB  (3 * STAGEB)

struct GemmP {
    const bf16 *Ah, *Al; long long As; int lda;
    const bf16 *Bh, *Bl; long long Bs; int ldb;
    float* Cf; bf16 *Ch, *Cl; long long Cs; int ldc;
    const float* bn;
    int K;
};

static __device__ __forceinline__ void issue_stage(
    uint32_t sbase, int slot,
    const bf16* __restrict__ Ah, const bf16* __restrict__ Al, int lda,
    const bf16* __restrict__ Bh, const bf16* __restrict__ Bl, int ldb,
    int k0, int tid) {
    uint32_t st = sbase + (uint32_t)slot * STAGEB;
#pragma unroll
    for (int i = 0; i < 8; i++) {
        int idx = tid + i * 256;              // 0..2047
        int half = idx >> 10;                 // 0 = A, 1 = B
        int r = (idx >> 3) & 127;
        int c = idx & 7;                      // chunk: 0-3 hi, 4-7 lo
        const bf16* base;
        int ld;
        if (half == 0) { base = (c < 4) ? Ah : Al; ld = lda; }
        else           { base = (c < 4) ? Bh : Bl; ld = ldb; }
        const char* src = (const char*)(base + (size_t)r * ld + k0) + (c & 3) * 16;
        uint32_t dst = st + (uint32_t)half * 16384u + (uint32_t)r * 128u
                     + (uint32_t)((c ^ (r & 7)) << 4);
        cp16(dst, src);
    }
}

__global__ __launch_bounds__(256, 2) void k_gemm(GemmP p) {
    extern __shared__ char smem[];
    const int tid = threadIdx.x;
    const int w = tid >> 5, l = tid & 31;
    const int wm = (w >> 2) * 64, wn = (w & 3) * 32;
    const int m0 = blockIdx.y * 128, n0 = blockIdx.x * 128;
    const int z = blockIdx.z;
    const uint32_t s0 = s2u(smem);

    const bf16* Abh = p.Ah + (size_t)z * p.As + (size_t)m0 * p.lda;
    const bf16* Abl = p.Al + (size_t)z * p.As + (size_t)m0 * p.lda;
    const bf16* Bbh = p.Bh + (size_t)z * p.Bs + (size_t)n0 * p.ldb;
    const bf16* Bbl = p.Bl + (size_t)z * p.Bs + (size_t)n0 * p.ldb;

    const uint32_t axor = (uint32_t)(l & 7);
    const uint32_t arow = (uint32_t)(wm + (l & 15));
    const uint32_t asel = (uint32_t)(l >> 4);           // A chunk half
    const uint32_t brow = (uint32_t)(wn + (l & 7) + ((l >> 4) & 1) * 8);
    const uint32_t bsel = (uint32_t)((l >> 3) & 1);     // B chunk half

    float acc[4][4][4];
#pragma unroll
    for (int t = 0; t < 4; t++)
#pragma unroll
        for (int j = 0; j < 4; j++)
#pragma unroll
            for (int r = 0; r < 4; r++) acc[t][j][r] = 0.f;

    const int NC = p.K >> 5;
    issue_stage(s0, 0, Abh, Abl, p.lda, Bbh, Bbl, p.ldb, 0, tid);
    asm volatile("cp.async.commit_group;" ::: "memory");
    issue_stage(s0, 1, Abh, Abl, p.lda, Bbh, Bbl, p.ldb, 32, tid);
    asm volatile("cp.async.commit_group;" ::: "memory");

    for (int c = 0; c < NC; c++) {
        asm volatile("cp.async.wait_group 1;" ::: "memory");
        __syncthreads();
        if (c + 2 < NC)
            issue_stage(s0, (c + 2) % 3, Abh, Abl, p.lda, Bbh, Bbl, p.ldb,
                        (c + 2) * 32, tid);
        asm volatile("cp.async.commit_group;" ::: "memory");

        uint32_t st = s0 + (uint32_t)(c % 3) * STAGEB;
#pragma unroll
        for (int ks = 0; ks < 2; ks++) {
            uint32_t bh[2][4], bl[2][4];
#pragma unroll
            for (int jp = 0; jp < 2; jp++) {
                uint32_t ba = st + 16384u + (brow + jp * 16u) * 128u
                            + (((2u * ks + bsel) ^ axor) << 4);
                ldsm4(bh[jp], ba);
                ldsm4(bl[jp], ba ^ 0x40u);
            }
#pragma unroll
            for (int t = 0; t < 4; t++) {
                uint32_t ah[4], al[4];
                uint32_t aa = st + (arow + t * 16u) * 128u
                            + (((2u * ks + asel) ^ axor) << 4);
                ldsm4(ah, aa);
                ldsm4(al, aa ^ 0x40u);
#pragma unroll
                for (int j = 0; j < 4; j++) {
                    uint32_t b0h[2] = { bh[j >> 1][(j & 1) * 2], bh[j >> 1][(j & 1) * 2 + 1] };
                    uint32_t b0l[2] = { bl[j >> 1][(j & 1) * 2], bl[j >> 1][(j & 1) * 2 + 1] };
                    mma16816(acc[t][j], ah, b0h);
                    mma16816(acc[t][j], ah, b0l);
                    mma16816(acc[t][j], al, b0h);
                }
            }
        }
    }

    float* Cf = p.Cf ? p.Cf + (size_t)z * p.Cs : (float*)0;
    bf16* Ch = p.Ch ? p.Ch + (size_t)z * p.Cs : (bf16*)0;
    bf16* Cl = p.Cl ? p.Cl + (size_t)z * p.Cs : (bf16*)0;
    const float* bn = p.bn;
#pragma unroll
    for (int t = 0; t < 4; t++) {
        int m = m0 + wm + t * 16 + (l >> 2);
#pragma unroll
        for (int j = 0; j < 4; j++) {
            int n = n0 + wn + j * 8 + (l & 3) * 2;
#pragma unroll
            for (int h2 = 0; h2 < 2; h2++) {
                float v0 = acc[t][j][h2 * 2], v1 = acc[t][j][h2 * 2 + 1];
                int mr = m + h2 * 8;
                if (bn) { v0 += bn[n]; v1 += bn[n + 1]; }
                if (Cf) *(float2*)(Cf + (size_t)mr * p.ldc + n) = make_float2(v0, v1);
                if (Ch) {
                    uint32_t hh = pack_bf(v0, v1);
                    *(uint32_t*)((char*)Ch + ((size_t)mr * p.ldc + n) * 2) = hh;
                    float l0 = v0 - __uint_as_float(hh << 16);
                    float l1 = v1 - __uint_as_float(hh & 0xFFFF0000u);
                    *(uint32_t*)((char*)Cl + ((size_t)mr * p.ldc + n) * 2) = pack_bf(l0, l1);
                }
            }
        }
    }
}

// ---------------- reductions -------------------------------------------------
static __device__ __forceinline__ float blockReduceSum256(float v) {
    __shared__ float sb[8];
#pragma unroll
    for (int o = 16; o > 0; o >>= 1) v += __shfl_xor_sync(0xffffffffu, v, o);
    __syncthreads();
    if ((threadIdx.x & 31) == 0) sb[threadIdx.x >> 5] = v;
    __syncthreads();
    float r = sb[0];
#pragma unroll
    for (int i = 1; i < 8; i++) r += sb[i];
    return r;
}
static __device__ __forceinline__ float blockReduceMax256(float v) {
    __shared__ float sb[8];
#pragma unroll
    for (int o = 16; o > 0; o >>= 1) v = fmaxf(v, __shfl_xor_sync(0xffffffffu, v, o));
    __syncthreads();
    if ((threadIdx.x & 31) == 0) sb[threadIdx.x >> 5] = v;
    __syncthreads();
    float r = sb[0];
#pragma unroll
    for (int i = 1; i < 8; i++) r = fmaxf(r, sb[i]);
    return r;
}

// ---------------- conversion / transpose kernels ------------------------------
__global__ void k_split(const float4* __restrict__ src, uint2* __restrict__ hi,
                        uint2* __restrict__ lo, int n4) {
    int i = blockIdx.x * 256 + threadIdx.x;
    if (i >= n4) return;
    float4 v = src[i];
    uint32_t h0 = pack_bf(v.x, v.y), h1 = pack_bf(v.z, v.w);
    float lx = v.x - __uint_as_float(h0 << 16);
    float ly = v.y - __uint_as_float(h0 & 0xFFFF0000u);
    float lz = v.z - __uint_as_float(h1 << 16);
    float lw = v.w - __uint_as_float(h1 & 0xFFFF0000u);
    hi[i] = make_uint2(h0, h1);
    lo[i] = make_uint2(pack_bf(lx, ly), pack_bf(lz, lw));
}

__global__ void k_trans_split(const float* __restrict__ src,
                              bf16* __restrict__ hi, bf16* __restrict__ lo,
                              int R, int C, long long ss, long long ds) {
    __shared__ float t[32][33];
    src += (size_t)blockIdx.z * ss;
    hi += (size_t)blockIdx.z * ds;
    lo += (size_t)blockIdx.z * ds;
    int c0 = blockIdx.x * 32, r0 = blockIdx.y * 32;
#pragma unroll
    for (int i = 0; i < 32; i += 8)
        t[threadIdx.y + i][threadIdx.x] =
            src[(size_t)(r0 + threadIdx.y + i) * C + c0 + threadIdx.x];
    __syncthreads();
#pragma unroll
    for (int i = 0; i < 32; i += 8) {
        float v = t[threadIdx.x][threadIdx.y + i];
        bf16 h = __float2bfloat16_rn(v);
        size_t o = (size_t)(c0 + threadIdx.y + i) * R + r0 + threadIdx.x;
        hi[o] = h;
        lo[o] = __float2bfloat16_rn(v - __bfloat162float(h));
    }
}

__global__ void k_reduce_split(const float* __restrict__ src, int Z, int total,
                               bf16* __restrict__ hi, bf16* __restrict__ lo) {
    int i = blockIdx.x * 256 + threadIdx.x;
    if (i >= total) return;
    float s = 0;
    for (int zz = 0; zz < Z; zz++) s += src[(size_t)zz * total + i];
    bf16 h = __float2bfloat16_rn(s);
    hi[i] = h;
    lo[i] = __float2bfloat16_rn(s - __bfloat162float(h));
}

// ---------------- small algebra kernels ---------------------------------------
__global__ void k_usum1(const float* __restrict__ x) {
    int e = blockIdx.x * 256 + threadIdx.x;
    int zc = blockIdx.y;
    float s = 0;
    for (int si = zc * 128; si < zc * 128 + 128; si++) s += x[(size_t)si * E_DIM + e];
    g_u32p[zc * E_DIM + e] = s;
}
__global__ void k_usum2() {
    int e = blockIdx.x * 256 + threadIdx.x;
    float s = 0;
    for (int zc = 0; zc < 32; zc++) s += g_u32p[zc * E_DIM + e];
    g_u[e] = s;
}
__global__ void k_qkbar(const float* __restrict__ Wq, const float* __restrict__ Wk) {
    int f = blockIdx.x, h = blockIdx.y;
    const float* Wrow = (blockIdx.z == 0 ? Wq : Wk) + ((size_t)h * E_DIM + f) * E_DIM;
    float s = 0;
    for (int i = threadIdx.x; i < E_DIM; i += 256) s += g_u[i] * Wrow[i];
    s = blockReduceSum256(s);
    if (threadIdx.x == 0) (blockIdx.z == 0 ? g_qbar : g_kbar)[h * E_DIM + f] = s;
}

__global__ __launch_bounds__(256, 4) void k_softfix(const float* __restrict__ bq,
                                                    const float* __restrict__ bk) {
    int row = blockIdx.x, h = row >> 10, e = row & 1023;
    float* p = g_A + (size_t)row * E_DIM;
    const float bke = bk[h * E_DIM + e], kbe = g_kbar[h * E_DIM + e];
    const float* qb = g_qbar + h * E_DIM;
    const float* bqh = bq + h * E_DIM;
    int tid = threadIdx.x;
    float v[4];
    float m = -1e30f;
#pragma unroll
    for (int i = 0; i < 4; i++) {
        int f = tid + i * 256;
        float s = p[f] + bke * (qb[f] + 4096.0f * bqh[f]) + kbe * bqh[f];
        v[i] = s * 0.03125f;
        m = fmaxf(m, v[i]);
    }
    m = blockReduceMax256(m);
    float sum = 0;
#pragma unroll
    for (int i = 0; i < 4; i++) { v[i] = __expf(v[i] - m); sum += v[i]; }
    sum = blockReduceSum256(sum);
    float inv = 1.0f / sum;
#pragma unroll
    for (int i = 0; i < 4; i++) p[tid + i * 256] = v[i] * inv;
}

__global__ void k_rvec1(const float* __restrict__ bv) {
    int f = blockIdx.x * 256 + threadIdx.x;
    int h = blockIdx.y, zc = blockIdx.z;
    const float* Ah = g_A + (size_t)h * E_DIM * E_DIM;
    const float* bvh = bv + h * E_DIM;
    float s = 0;
    for (int e = zc * 128; e < zc * 128 + 128; e++)
        s += bvh[e] * Ah[(size_t)e * E_DIM + f];
    g_r8[(zc * H_DIM + h) * E_DIM + f] = s;
}
__global__ void k_rvec2() {
    int i = blockIdx.x * 256 + threadIdx.x;
    float s = 0;
    for (int zc = 0; zc < 8; zc++) s += g_r8[zc * H_DIM * E_DIM + i];
    g_r[i] = s;
}
__global__ void k_cvec(const float* __restrict__ Wz, const float* __restrict__ bz) {
    int o = blockIdx.x;
    const float* wrow = Wz + (size_t)o * HE_DIM;
    float s = 0;
    for (int i = threadIdx.x; i < HE_DIM; i += 256) s += g_r[i] * wrow[i];
    s = blockReduceSum256(s);
    if (threadIdx.x == 0) g_c[o] = bz[o] + s;
}

// LN1 = LN(O)*g1+b1 + x  (writes fp32 + bf16 hi/lo)
__global__ __launch_bounds__(256, 4)
void k_ln1(const float* __restrict__ x, const float* __restrict__ g,
           const float* __restrict__ b) {
    const size_t row = blockIdx.x;
    const int tid = threadIdx.x;
    const float* p = g_O + row * E_DIM;
    float v[4];
    float s = 0.f;
#pragma unroll
    for (int i = 0; i < 4; i++) { v[i] = p[tid + i * 256]; s += v[i]; }
    const float mean = blockReduceSum256(s) * (1.0f / E_DIM);
    float q = 0.f;
#pragma unroll
    for (int i = 0; i < 4; i++) { const float d = v[i] - mean; q += d * d; }
    const float var = blockReduceSum256(q) * (1.0f / E_DIM);
    const float rstd = rsqrtf(var + 1e-5f);
#pragma unroll
    for (int i = 0; i < 4; i++) {
        const int idx = tid + i * 256;
        float o = (v[i] - mean) * rstd * g[idx] + b[idx] + x[row * E_DIM + idx];
        g_LN1[row * E_DIM + idx] = o;
        bf16 h = __float2bfloat16_rn(o);
        b_L1h[row * E_DIM + idx] = h;
        b_L1l[row * E_DIM + idx] = __float2bfloat16_rn(o - __bfloat162float(h));
    }
}

__global__ __launch_bounds__(256, 4)
void k_ln2(const float* __restrict__ g, const float* __restrict__ b,
           float* __restrict__ out) {
    const size_t row = blockIdx.x;
    const int tid = threadIdx.x;
    const float* p = g_FN + row * E_DIM;
    float v[4];
    float s = 0.f;
#pragma unroll
    for (int i = 0; i < 4; i++) { v[i] = p[tid + i * 256]; s += v[i]; }
    const float mean = blockReduceSum256(s) * (1.0f / E_DIM);
    float q = 0.f;
#pragma unroll
    for (int i = 0; i < 4; i++) { const float d = v[i] - mean; q += d * d; }
    const float var = blockReduceSum256(q) * (1.0f / E_DIM);
    const float rstd = rsqrtf(var + 1e-5f);
#pragma unroll
    for (int i = 0; i < 4; i++) {
        const int idx = tid + i * 256;
        out[row * E_DIM + idx] =
            (v[i] - mean) * rstd * g[idx] + b[idx] + g_LN1[row * E_DIM + idx];
    }
}

// ============================================================================
// Launch
// ============================================================================
#define SYM(v, s) cudaGetSymbolAddress((void**)&v, s)

extern "C" void kernel_launch(void* const* d_in, const int* in_sizes, int n_in,
                              void* d_out, int out_size) {
    (void)in_sizes; (void)n_in; (void)out_size;
    const float* x  = (const float*)d_in[0];
    const float* Wq = (const float*)d_in[1];
    const float* bq = (const float*)d_in[2];
    const float* Wk = (const float*)d_in[3];
    const float* bk = (const float*)d_in[4];
    const float* Wv = (const float*)d_in[5];
    const float* bv = (const float*)d_in[6];
    const float* Wz = (const float*)d_in[7];
    const float* bz = (const float*)d_in[8];
    const float* g1 = (const float*)d_in[9];
    const float* b1 = (const float*)d_in[10];
    const float* Wf = (const float*)d_in[11];
    const float* bf = (const float*)d_in[12];
    const float* g2 = (const float*)d_in[13];
    const float* b2 = (const float*)d_in[14];
    float* out = (float*)d_out;

    cudaFuncSetAttribute(k_gemm, cudaFuncAttributeMaxDynamicSharedMemorySize, SMEMB);

    float *dA, *dG4, *dPT8, *dO, *dc;
    SYM(dA, g_A); SYM(dG4, g_G4); SYM(dPT8, g_PT8); SYM(dO, g_O); SYM(dc, g_c);
    bf16 *xh, *xl, *xTh, *xTl, *Gh, *Gl, *Wkh, *Wkl, *Wqh, *Wql, *Th, *Tl;
    bf16 *ATh, *ATl, *WvTh, *WvTl, *Mh, *Ml, *Wzh, *Wzl, *PTh, *PTl;
    bf16 *L1h, *L1l, *Wfh, *Wfl;
    SYM(xh, b_xh); SYM(xl, b_xl); SYM(xTh, b_xTh); SYM(xTl, b_xTl);
    SYM(Gh, b_Gh); SYM(Gl, b_Gl); SYM(Wkh, b_Wkh); SYM(Wkl, b_Wkl);
    SYM(Wqh, b_Wqh); SYM(Wql, b_Wql); SYM(Th, b_Th); SYM(Tl, b_Tl);
    SYM(ATh, b_ATh); SYM(ATl, b_ATl); SYM(WvTh, b_WvTh); SYM(WvTl, b_WvTl);
    SYM(Mh, b_Mh); SYM(Ml, b_Ml); SYM(Wzh, b_Wzh); SYM(Wzl, b_Wzl);
    SYM(PTh, b_PTh); SYM(PTl, b_PTl); SYM(L1h, b_L1h); SYM(L1l, b_L1l);
    SYM(Wfh, b_Wfh); SYM(Wfl, b_Wfl);

    const long long EE = (long long)E_DIM * E_DIM;
    dim3 tb(32, 8);

    // ---- operand preparation ----
    k_split<<<(S_DIM * E_DIM / 4 + 255) / 256, 256>>>((const float4*)x, (uint2*)xh, (uint2*)xl, S_DIM * E_DIM / 4);
    k_trans_split<<<dim3(E_DIM / 32, S_DIM / 32, 1), tb>>>(x, xTh, xTl, S_DIM, E_DIM, 0, 0);
    k_usum1<<<dim3(4, 32), 256>>>(x);
    k_usum2<<<4, 256>>>();
    k_split<<<(int)(H_DIM * EE / 4 + 255) / 256, 256>>>((const float4*)Wk, (uint2*)Wkh, (uint2*)Wkl, (int)(H_DIM * EE / 4));
    k_split<<<(int)(H_DIM * EE / 4 + 255) / 256, 256>>>((const float4*)Wq, (uint2*)Wqh, (uint2*)Wql, (int)(H_DIM * EE / 4));
    k_split<<<(int)(H_DIM * EE / 4 + 255) / 256, 256>>>((const float4*)Wz, (uint2*)Wzh, (uint2*)Wzl, (int)(H_DIM * EE / 4));
    k_split<<<(int)(EE / 4 + 255) / 256, 256>>>((const float4*)Wf, (uint2*)Wfh, (uint2*)Wfl, (int)(EE / 4));
    k_trans_split<<<dim3(32, 32, H_DIM), tb>>>(Wv, WvTh, WvTl, E_DIM, E_DIM, EE, EE);

    // ---- G = x^T x (split-K4) ----
    { GemmP p{xTh, xTl, 1024, S_DIM, xTh, xTl, 1024, S_DIM,
              dG4, 0, 0, EE, E_DIM, nullptr, 1024};
      k_gemm<<<dim3(8, 8, 4), 256, SMEMB>>>(p); }
    k_reduce_split<<<(int)(EE / 256), 256>>>(dG4, 4, (int)EE, Gh, Gl);

    // ---- T_h = Wk_h @ G ----
    { GemmP p{Wkh, Wkl, EE, E_DIM, Gh, Gl, 0, E_DIM,
              0, Th, Tl, EE, E_DIM, nullptr, E_DIM};
      k_gemm<<<dim3(8, 8, H_DIM), 256, SMEMB>>>(p); }
    // ---- scores_h = T_h @ Wq_h^T (raw fp32) ----
    { GemmP p{Th, Tl, EE, E_DIM, Wqh, Wql, EE, E_DIM,
              dA, 0, 0, EE, E_DIM, nullptr, E_DIM};
      k_gemm<<<dim3(8, 8, H_DIM), 256, SMEMB>>>(p); }

    // ---- bias fixup + softmax ----
    k_qkbar<<<dim3(E_DIM, H_DIM, 2), 256>>>(Wq, Wk);
    k_softfix<<<H_DIM * E_DIM, 256>>>(bq, bk);

    // ---- Z-path bias constants ----
    k_rvec1<<<dim3(4, H_DIM, 8), 256>>>(bv);
    k_rvec2<<<HE_DIM / 256, 256>>>();
    k_cvec<<<E_DIM, 256>>>(Wz, bz);

    // ---- A^T, M_h = Wv_h^T A_h, PT8_h, reduce ----
    k_trans_split<<<dim3(32, 32, H_DIM), tb>>>(dA, ATh, ATl, E_DIM, E_DIM, EE, EE);
    { GemmP p{WvTh, WvTl, EE, E_DIM, ATh, ATl, EE, E_DIM,
              0, Mh, Ml, EE, E_DIM, nullptr, E_DIM};
      k_gemm<<<dim3(8, 8, H_DIM), 256, SMEMB>>>(p); }
    { GemmP p{Wzh, Wzl, E_DIM, HE_DIM, Mh, Ml, EE, E_DIM,
              dPT8, 0, 0, EE, E_DIM, nullptr, E_DIM};
      k_gemm<<<dim3(8, 8, H_DIM), 256, SMEMB>>>(p); }
    k_reduce_split<<<(int)(EE / 256), 256>>>(dPT8, 8, (int)EE, PTh, PTl);

    // ---- O = x @ P + c ----
    { GemmP p{xh, xl, 0, E_DIM, PTh, PTl, 0, E_DIM,
              dO, 0, 0, 0, E_DIM, dc, E_DIM};
      k_gemm<<<dim3(8, 32, 1), 256, SMEMB>>>(p); }
    k_ln1<<<S_DIM, 256>>>(x, g1, b1);

    // ---- FN = LN1 @ Wf^T + bf ----
    { GemmP p{L1h, L1l, 0, E_DIM, Wfh, Wfl, 0, E_DIM,
              (float*)0, 0, 0, 0, E_DIM, bf, E_DIM};
      GemmP q = p; q.Cf = nullptr;
      float* dFN; SYM(dFN, g_FN);
      q.Cf = dFN;
      k_gemm<<<dim3(8, 32, 1), 256, SMEMB>>>(q); }
    k_ln2<<<S_DIM, 256>>>(g2, b2, out);
}

// round 6
// speedup vs baseline: 10.2298x; 1.0573x over previous
#include <cuda_runtime.h>
#include <cuda_bf16.h>
#include <cstdint>

#define S_DIM 4096
#define E_DIM 1024
#define H_DIM 8
#define HE_DIM 8192
typedef __nv_bfloat16 bf16;

// ---------------- fp32 scratch ----------------------------------------------
__device__ float g_A  [(size_t)H_DIM * E_DIM * E_DIM];  // scores->softmax 32MB
__device__ float g_G4 [(size_t)4 * E_DIM * E_DIM];      // split-K partials
__device__ float g_PT8[(size_t)H_DIM * E_DIM * E_DIM];  // per-head P^T partials
__device__ float g_O  [(size_t)S_DIM * E_DIM];
__device__ float g_LN1[(size_t)S_DIM * E_DIM];
__device__ float g_FN [(size_t)S_DIM * E_DIM];
__device__ float g_u32p[32 * E_DIM];
__device__ float g_u  [E_DIM];
__device__ float g_qbar[H_DIM * E_DIM];
__device__ float g_kbar[H_DIM * E_DIM];
__device__ float g_r8 [8 * H_DIM * E_DIM];
__device__ float g_r  [H_DIM * E_DIM];
__device__ float g_c  [E_DIM];

// ---------------- bf16 hi/lo operand buffers ---------------------------------
__device__ bf16 b_xh [(size_t)S_DIM * E_DIM],  b_xl [(size_t)S_DIM * E_DIM];
__device__ bf16 b_xTh[(size_t)E_DIM * S_DIM],  b_xTl[(size_t)E_DIM * S_DIM];
__device__ bf16 b_Gh [(size_t)E_DIM * E_DIM],  b_Gl [(size_t)E_DIM * E_DIM];
__device__ bf16 b_Wkh[(size_t)H_DIM * E_DIM * E_DIM], b_Wkl[(size_t)H_DIM * E_DIM * E_DIM];
__device__ bf16 b_Wqh[(size_t)H_DIM * E_DIM * E_DIM], b_Wql[(size_t)H_DIM * E_DIM * E_DIM];
__device__ bf16 b_Th [(size_t)H_DIM * E_DIM * E_DIM], b_Tl [(size_t)H_DIM * E_DIM * E_DIM];
__device__ bf16 b_ATh[(size_t)H_DIM * E_DIM * E_DIM], b_ATl[(size_t)H_DIM * E_DIM * E_DIM];
__device__ bf16 b_WvTh[(size_t)H_DIM * E_DIM * E_DIM], b_WvTl[(size_t)H_DIM * E_DIM * E_DIM];
__device__ bf16 b_Mh [(size_t)H_DIM * E_DIM * E_DIM], b_Ml [(size_t)H_DIM * E_DIM * E_DIM];
__device__ bf16 b_Wzh[(size_t)H_DIM * E_DIM * E_DIM], b_Wzl[(size_t)H_DIM * E_DIM * E_DIM];
__device__ bf16 b_PTh[(size_t)E_DIM * E_DIM],  b_PTl[(size_t)E_DIM * E_DIM];
__device__ bf16 b_L1h[(size_t)S_DIM * E_DIM],  b_L1l[(size_t)S_DIM * E_DIM];
__device__ bf16 b_Wfh[(size_t)E_DIM * E_DIM],  b_Wfl[(size_t)E_DIM * E_DIM];

// ---------------- helpers ----------------------------------------------------
static __device__ __forceinline__ uint32_t s2u(const void* p) {
    uint32_t a;
    asm("{ .reg .u64 t; cvta.to.shared.u64 t, %1; cvt.u32.u64 %0, t; }"
        : "=r"(a) : "l"(p));
    return a;
}
static __device__ __forceinline__ uint32_t pack_bf(float a, float b) {
    uint32_t r;
    asm("cvt.rn.bf16x2.f32 %0, %1, %2;" : "=r"(r) : "f"(b), "f"(a));
    return r;
}
static __device__ __forceinline__ void ldsm4(uint32_t* r, uint32_t addr) {
    asm volatile("ldmatrix.sync.aligned.m8n8.x4.shared.b16 {%0,%1,%2,%3}, [%4];"
                 : "=r"(r[0]), "=r"(r[1]), "=r"(r[2]), "=r"(r[3]) : "r"(addr));
}
static __device__ __forceinline__ void mma16816(float* d, const uint32_t* a,
                                                const uint32_t* b) {
    asm volatile(
        "mma.sync.aligned.m16n8k16.row.col.f32.bf16.bf16.f32 "
        "{%0,%1,%2,%3},{%4,%5,%6,%7},{%8,%9},{%0,%1,%2,%3};"
        : "+f"(d[0]), "+f"(d[1]), "+f"(d[2]), "+f"(d[3])
        : "r"(a[0]), "r"(a[1]), "r"(a[2]), "r"(a[3]), "r"(b[0]), "r"(b[1]));
}
static __device__ __forceinline__ void cp16(uint32_t dst, const void* src) {
    asm volatile("cp.async.cg.shared.global [%0], [%1], 16;"
                 :: "r"(dst), "l"(src));
}

// ============================================================================
// bf16 hi/lo cp.async GEMM (NT): C[m,n] = sum_k A[m,k]*B[n,k] (+bn[n])
// CTA 128x128, BK=32, 256 threads (8 warps 2x4, warp tile 64x32), 3 stages.
// ============================================================================
#define STAGEB 32768
#define SMEMB  (3 * STAGEB)

struct GemmP {
    const bf16 *Ah, *Al; long long As; int lda;
    const bf16 *Bh, *Bl; long long Bs; int ldb;
    float* Cf; bf16 *Ch, *Cl; long long Cs; int ldc;
    const float* bn;
    int K;
};

static __device__ __forceinline__ void issue_stage(
    uint32_t sbase, int slot,
    const bf16* __restrict__ Ah, const bf16* __restrict__ Al, int lda,
    const bf16* __restrict__ Bh, const bf16* __restrict__ Bl, int ldb,
    int k0, int tid) {
    uint32_t st = sbase + (uint32_t)slot * STAGEB;
#pragma unroll
    for (int i = 0; i < 8; i++) {
        int idx = tid + i * 256;              // 0..2047
        int half = idx >> 10;                 // 0 = A, 1 = B
        int r = (idx >> 3) & 127;
        int c = idx & 7;                      // chunk: 0-3 hi, 4-7 lo
        const bf16* base;
        int ld;
        if (half == 0) { base = (c < 4) ? Ah : Al; ld = lda; }
        else           { base = (c < 4) ? Bh : Bl; ld = ldb; }
        const char* src = (const char*)(base + (size_t)r * ld + k0) + (c & 3) * 16;
        uint32_t dst = st + (uint32_t)half * 16384u + (uint32_t)r * 128u
                     + (uint32_t)((c ^ (r & 7)) << 4);
        cp16(dst, src);
    }
}

__global__ __launch_bounds__(256, 2) void k_gemm(GemmP p) {
    extern __shared__ char smem[];
    const int tid = threadIdx.x;
    const int w = tid >> 5, l = tid & 31;
    const int wm = (w >> 2) * 64, wn = (w & 3) * 32;
    const int m0 = blockIdx.y * 128, n0 = blockIdx.x * 128;
    const int z = blockIdx.z;
    const uint32_t s0 = s2u(smem);

    const bf16* Abh = p.Ah + (size_t)z * p.As + (size_t)m0 * p.lda;
    const bf16* Abl = p.Al + (size_t)z * p.As + (size_t)m0 * p.lda;
    const bf16* Bbh = p.Bh + (size_t)z * p.Bs + (size_t)n0 * p.ldb;
    const bf16* Bbl = p.Bl + (size_t)z * p.Bs + (size_t)n0 * p.ldb;

    const uint32_t axor = (uint32_t)(l & 7);
    const uint32_t arow = (uint32_t)(wm + (l & 15));
    const uint32_t asel = (uint32_t)(l >> 4);
    const uint32_t brow = (uint32_t)(wn + (l & 7) + ((l >> 4) & 1) * 8);
    const uint32_t bsel = (uint32_t)((l >> 3) & 1);

    float acc[4][4][4];
#pragma unroll
    for (int t = 0; t < 4; t++)
#pragma unroll
        for (int j = 0; j < 4; j++)
#pragma unroll
            for (int r = 0; r < 4; r++) acc[t][j][r] = 0.f;

    const int NC = p.K >> 5;
    issue_stage(s0, 0, Abh, Abl, p.lda, Bbh, Bbl, p.ldb, 0, tid);
    asm volatile("cp.async.commit_group;" ::: "memory");
    issue_stage(s0, 1, Abh, Abl, p.lda, Bbh, Bbl, p.ldb, 32, tid);
    asm volatile("cp.async.commit_group;" ::: "memory");

    for (int c = 0; c < NC; c++) {
        asm volatile("cp.async.wait_group 1;" ::: "memory");
        __syncthreads();
        if (c + 2 < NC)
            issue_stage(s0, (c + 2) % 3, Abh, Abl, p.lda, Bbh, Bbl, p.ldb,
                        (c + 2) * 32, tid);
        asm volatile("cp.async.commit_group;" ::: "memory");

        uint32_t st = s0 + (uint32_t)(c % 3) * STAGEB;
#pragma unroll
        for (int ks = 0; ks < 2; ks++) {
            uint32_t bh[2][4], bl[2][4];
#pragma unroll
            for (int jp = 0; jp < 2; jp++) {
                uint32_t ba = st + 16384u + (brow + jp * 16u) * 128u
                            + (((2u * ks + bsel) ^ axor) << 4);
                ldsm4(bh[jp], ba);
                ldsm4(bl[jp], ba ^ 0x40u);
            }
#pragma unroll
            for (int t = 0; t < 4; t++) {
                uint32_t ah[4], al[4];
                uint32_t aa = st + (arow + t * 16u) * 128u
                            + (((2u * ks + asel) ^ axor) << 4);
                ldsm4(ah, aa);
                ldsm4(al, aa ^ 0x40u);
#pragma unroll
                for (int j = 0; j < 4; j++) {
                    uint32_t b0h[2] = { bh[j >> 1][(j & 1) * 2], bh[j >> 1][(j & 1) * 2 + 1] };
                    uint32_t b0l[2] = { bl[j >> 1][(j & 1) * 2], bl[j >> 1][(j & 1) * 2 + 1] };
                    mma16816(acc[t][j], ah, b0h);
                    mma16816(acc[t][j], ah, b0l);
                    mma16816(acc[t][j], al, b0h);
                }
            }
        }
    }

    float* Cf = p.Cf ? p.Cf + (size_t)z * p.Cs : (float*)0;
    bf16* Ch = p.Ch ? p.Ch + (size_t)z * p.Cs : (bf16*)0;
    bf16* Cl = p.Cl ? p.Cl + (size_t)z * p.Cs : (bf16*)0;
    const float* bn = p.bn;
#pragma unroll
    for (int t = 0; t < 4; t++) {
        int m = m0 + wm + t * 16 + (l >> 2);
#pragma unroll
        for (int j = 0; j < 4; j++) {
            int n = n0 + wn + j * 8 + (l & 3) * 2;
#pragma unroll
            for (int h2 = 0; h2 < 2; h2++) {
                float v0 = acc[t][j][h2 * 2], v1 = acc[t][j][h2 * 2 + 1];
                int mr = m + h2 * 8;
                if (bn) { v0 += bn[n]; v1 += bn[n + 1]; }
                if (Cf) *(float2*)(Cf + (size_t)mr * p.ldc + n) = make_float2(v0, v1);
                if (Ch) {
                    uint32_t hh = pack_bf(v0, v1);
                    *(uint32_t*)((char*)Ch + ((size_t)mr * p.ldc + n) * 2) = hh;
                    float l0 = v0 - __uint_as_float(hh << 16);
                    float l1 = v1 - __uint_as_float(hh & 0xFFFF0000u);
                    *(uint32_t*)((char*)Cl + ((size_t)mr * p.ldc + n) * 2) = pack_bf(l0, l1);
                }
            }
        }
    }
}

// ---------------- reductions -------------------------------------------------
static __device__ __forceinline__ float blockReduceSum256(float v) {
    __shared__ float sb[8];
#pragma unroll
    for (int o = 16; o > 0; o >>= 1) v += __shfl_xor_sync(0xffffffffu, v, o);
    __syncthreads();
    if ((threadIdx.x & 31) == 0) sb[threadIdx.x >> 5] = v;
    __syncthreads();
    float r = sb[0];
#pragma unroll
    for (int i = 1; i < 8; i++) r += sb[i];
    return r;
}
static __device__ __forceinline__ float blockReduceMax256(float v) {
    __shared__ float sb[8];
#pragma unroll
    for (int o = 16; o > 0; o >>= 1) v = fmaxf(v, __shfl_xor_sync(0xffffffffu, v, o));
    __syncthreads();
    if ((threadIdx.x & 31) == 0) sb[threadIdx.x >> 5] = v;
    __syncthreads();
    float r = sb[0];
#pragma unroll
    for (int i = 1; i < 8; i++) r = fmaxf(r, sb[i]);
    return r;
}

// ---------------- conversion / transpose kernels ------------------------------
__global__ void k_split(const float4* __restrict__ src, uint2* __restrict__ hi,
                        uint2* __restrict__ lo, int n4) {
    int i = blockIdx.x * 256 + threadIdx.x;
    if (i >= n4) return;
    float4 v = src[i];
    uint32_t h0 = pack_bf(v.x, v.y), h1 = pack_bf(v.z, v.w);
    float lx = v.x - __uint_as_float(h0 << 16);
    float ly = v.y - __uint_as_float(h0 & 0xFFFF0000u);
    float lz = v.z - __uint_as_float(h1 << 16);
    float lw = v.w - __uint_as_float(h1 & 0xFFFF0000u);
    hi[i] = make_uint2(h0, h1);
    lo[i] = make_uint2(pack_bf(lx, ly), pack_bf(lz, lw));
}

__global__ void k_trans_split(const float* __restrict__ src,
                              bf16* __restrict__ hi, bf16* __restrict__ lo,
                              int R, int C, long long ss, long long ds) {
    __shared__ float t[32][33];
    src += (size_t)blockIdx.z * ss;
    hi += (size_t)blockIdx.z * ds;
    lo += (size_t)blockIdx.z * ds;
    int c0 = blockIdx.x * 32, r0 = blockIdx.y * 32;
#pragma unroll
    for (int i = 0; i < 32; i += 8)
        t[threadIdx.y + i][threadIdx.x] =
            src[(size_t)(r0 + threadIdx.y + i) * C + c0 + threadIdx.x];
    __syncthreads();
#pragma unroll
    for (int i = 0; i < 32; i += 8) {
        float v = t[threadIdx.x][threadIdx.y + i];
        bf16 h = __float2bfloat16_rn(v);
        size_t o = (size_t)(c0 + threadIdx.y + i) * R + r0 + threadIdx.x;
        hi[o] = h;
        lo[o] = __float2bfloat16_rn(v - __bfloat162float(h));
    }
}

__global__ void k_reduce_split(const float* __restrict__ src, int Z, int total,
                               bf16* __restrict__ hi, bf16* __restrict__ lo) {
    int i = blockIdx.x * 256 + threadIdx.x;
    if (i >= total) return;
    float s = 0;
    for (int zz = 0; zz < Z; zz++) s += src[(size_t)zz * total + i];
    bf16 h = __float2bfloat16_rn(s);
    hi[i] = h;
    lo[i] = __float2bfloat16_rn(s - __bfloat162float(h));
}

// ---------------- small algebra kernels ---------------------------------------
__global__ void k_usum1(const float* __restrict__ x) {
    int e = blockIdx.x * 256 + threadIdx.x;
    int zc = blockIdx.y;
    float s = 0;
    for (int si = zc * 128; si < zc * 128 + 128; si++) s += x[(size_t)si * E_DIM + e];
    g_u32p[zc * E_DIM + e] = s;
}
__global__ void k_usum2() {
    int e = blockIdx.x * 256 + threadIdx.x;
    float s = 0;
    for (int zc = 0; zc < 32; zc++) s += g_u32p[zc * E_DIM + e];
    g_u[e] = s;
}
__global__ void k_qkbar(const float* __restrict__ Wq, const float* __restrict__ Wk) {
    int f = blockIdx.x, h = blockIdx.y;
    const float* Wrow = (blockIdx.z == 0 ? Wq : Wk) + ((size_t)h * E_DIM + f) * E_DIM;
    float s = 0;
    for (int i = threadIdx.x; i < E_DIM; i += 256) s += g_u[i] * Wrow[i];
    s = blockReduceSum256(s);
    if (threadIdx.x == 0) (blockIdx.z == 0 ? g_qbar : g_kbar)[h * E_DIM + f] = s;
}

__global__ __launch_bounds__(256, 4) void k_softfix(const float* __restrict__ bq,
                                                    const float* __restrict__ bk) {
    int row = blockIdx.x, h = row >> 10, e = row & 1023;
    float* p = g_A + (size_t)row * E_DIM;
    const float bke = bk[h * E_DIM + e], kbe = g_kbar[h * E_DIM + e];
    const float* qb = g_qbar + h * E_DIM;
    const float* bqh = bq + h * E_DIM;
    int tid = threadIdx.x;
    float v[4];
    float m = -1e30f;
#pragma unroll
    for (int i = 0; i < 4; i++) {
        int f = tid + i * 256;
        float s = p[f] + bke * (qb[f] + 4096.0f * bqh[f]) + kbe * bqh[f];
        v[i] = s * 0.03125f;
        m = fmaxf(m, v[i]);
    }
    m = blockReduceMax256(m);
    float sum = 0;
#pragma unroll
    for (int i = 0; i < 4; i++) { v[i] = __expf(v[i] - m); sum += v[i]; }
    sum = blockReduceSum256(sum);
    float inv = 1.0f / sum;
#pragma unroll
    for (int i = 0; i < 4; i++) p[tid + i * 256] = v[i] * inv;
}

__global__ void k_rvec1(const float* __restrict__ bv) {
    int f = blockIdx.x * 256 + threadIdx.x;
    int h = blockIdx.y, zc = blockIdx.z;
    const float* Ah = g_A + (size_t)h * E_DIM * E_DIM;
    const float* bvh = bv + h * E_DIM;
    float s = 0;
    for (int e = zc * 128; e < zc * 128 + 128; e++)
        s += bvh[e] * Ah[(size_t)e * E_DIM + f];
    g_r8[(zc * H_DIM + h) * E_DIM + f] = s;
}
__global__ void k_rvec2() {
    int i = blockIdx.x * 256 + threadIdx.x;
    float s = 0;
    for (int zc = 0; zc < 8; zc++) s += g_r8[zc * H_DIM * E_DIM + i];
    g_r[i] = s;
}
__global__ void k_cvec(const float* __restrict__ Wz, const float* __restrict__ bz) {
    int o = blockIdx.x;
    const float* wrow = Wz + (size_t)o * HE_DIM;
    float s = 0;
    for (int i = threadIdx.x; i < HE_DIM; i += 256) s += g_r[i] * wrow[i];
    s = blockReduceSum256(s);
    if (threadIdx.x == 0) g_c[o] = bz[o] + s;
}

// LN1 = LN(O)*g1+b1 + x  (writes fp32 + bf16 hi/lo)
__global__ __launch_bounds__(256, 4)
void k_ln1(const float* __restrict__ x, const float* __restrict__ g,
           const float* __restrict__ b) {
    const size_t row = blockIdx.x;
    const int tid = threadIdx.x;
    const float* p = g_O + row * E_DIM;
    float v[4];
    float s = 0.f;
#pragma unroll
    for (int i = 0; i < 4; i++) { v[i] = p[tid + i * 256]; s += v[i]; }
    const float mean = blockReduceSum256(s) * (1.0f / E_DIM);
    float q = 0.f;
#pragma unroll
    for (int i = 0; i < 4; i++) { const float d = v[i] - mean; q += d * d; }
    const float var = blockReduceSum256(q) * (1.0f / E_DIM);
    const float rstd = rsqrtf(var + 1e-5f);
#pragma unroll
    for (int i = 0; i < 4; i++) {
        const int idx = tid + i * 256;
        float o = (v[i] - mean) * rstd * g[idx] + b[idx] + x[row * E_DIM + idx];
        g_LN1[row * E_DIM + idx] = o;
        bf16 h = __float2bfloat16_rn(o);
        b_L1h[row * E_DIM + idx] = h;
        b_L1l[row * E_DIM + idx] = __float2bfloat16_rn(o - __bfloat162float(h));
    }
}

__global__ __launch_bounds__(256, 4)
void k_ln2(const float* __restrict__ g, const float* __restrict__ b,
           float* __restrict__ out) {
    const size_t row = blockIdx.x;
    const int tid = threadIdx.x;
    const float* p = g_FN + row * E_DIM;
    float v[4];
    float s = 0.f;
#pragma unroll
    for (int i = 0; i < 4; i++) { v[i] = p[tid + i * 256]; s += v[i]; }
    const float mean = blockReduceSum256(s) * (1.0f / E_DIM);
    float q = 0.f;
#pragma unroll
    for (int i = 0; i < 4; i++) { const float d = v[i] - mean; q += d * d; }
    const float var = blockReduceSum256(q) * (1.0f / E_DIM);
    const float rstd = rsqrtf(var + 1e-5f);
#pragma unroll
    for (int i = 0; i < 4; i++) {
        const int idx = tid + i * 256;
        out[row * E_DIM + idx] =
            (v[i] - mean) * rstd * g[idx] + b[idx] + g_LN1[row * E_DIM + idx];
    }
}

// ============================================================================
// Launch — fork/join two-stream graph (record ALWAYS precedes wait)
// ============================================================================
#define SYM(v, s) cudaGetSymbolAddress((void**)&v, s)

static cudaStream_t g_s1;
static cudaEvent_t evFork, evPrep, evSoft, evC;
static bool g_init = false;

extern "C" void kernel_launch(void* const* d_in, const int* in_sizes, int n_in,
                              void* d_out, int out_size) {
    (void)in_sizes; (void)n_in; (void)out_size;
    const float* x  = (const float*)d_in[0];
    const float* Wq = (const float*)d_in[1];
    const float* bq = (const float*)d_in[2];
    const float* Wk = (const float*)d_in[3];
    const float* bk = (const float*)d_in[4];
    const float* Wv = (const float*)d_in[5];
    const float* bv = (const float*)d_in[6];
    const float* Wz = (const float*)d_in[7];
    const float* bz = (const float*)d_in[8];
    const float* g1 = (const float*)d_in[9];
    const float* b1 = (const float*)d_in[10];
    const float* Wf = (const float*)d_in[11];
    const float* bf = (const float*)d_in[12];
    const float* g2 = (const float*)d_in[13];
    const float* b2 = (const float*)d_in[14];
    float* out = (float*)d_out;

    if (!g_init) {
        cudaFuncSetAttribute(k_gemm, cudaFuncAttributeMaxDynamicSharedMemorySize, SMEMB);
        cudaStreamCreateWithFlags(&g_s1, cudaStreamNonBlocking);
        cudaEventCreateWithFlags(&evFork, cudaEventDisableTiming);
        cudaEventCreateWithFlags(&evPrep, cudaEventDisableTiming);
        cudaEventCreateWithFlags(&evSoft, cudaEventDisableTiming);
        cudaEventCreateWithFlags(&evC,    cudaEventDisableTiming);
        g_init = true;
    }

    float *dA, *dG4, *dPT8, *dO, *dc, *dFN;
    SYM(dA, g_A); SYM(dG4, g_G4); SYM(dPT8, g_PT8); SYM(dO, g_O); SYM(dc, g_c);
    SYM(dFN, g_FN);
    bf16 *xh, *xl, *xTh, *xTl, *Gh, *Gl, *Wkh, *Wkl, *Wqh, *Wql, *Th, *Tl;
    bf16 *ATh, *ATl, *WvTh, *WvTl, *Mh, *Ml, *Wzh, *Wzl, *PTh, *PTl;
    bf16 *L1h, *L1l, *Wfh, *Wfl;
    SYM(xh, b_xh); SYM(xl, b_xl); SYM(xTh, b_xTh); SYM(xTl, b_xTl);
    SYM(Gh, b_Gh); SYM(Gl, b_Gl); SYM(Wkh, b_Wkh); SYM(Wkl, b_Wkl);
    SYM(Wqh, b_Wqh); SYM(Wql, b_Wql); SYM(Th, b_Th); SYM(Tl, b_Tl);
    SYM(ATh, b_ATh); SYM(ATl, b_ATl); SYM(WvTh, b_WvTh); SYM(WvTl, b_WvTl);
    SYM(Mh, b_Mh); SYM(Ml, b_Ml); SYM(Wzh, b_Wzh); SYM(Wzl, b_Wzl);
    SYM(PTh, b_PTh); SYM(PTl, b_PTl); SYM(L1h, b_L1h); SYM(L1l, b_L1l);
    SYM(Wfh, b_Wfh); SYM(Wfl, b_Wfl);

    const long long EE = (long long)E_DIM * E_DIM;
    dim3 tb(32, 8);
    cudaStream_t s0 = 0, s1 = g_s1;

    // ---- fork: side stream joins capture after this record ----
    cudaEventRecord(evFork, s0);
    cudaStreamWaitEvent(s1, evFork, 0);

    // ======== side stream phase 1: all input-only prep ========
    k_split<<<(int)(H_DIM * EE / 4 + 255) / 256, 256, 0, s1>>>((const float4*)Wk, (uint2*)Wkh, (uint2*)Wkl, (int)(H_DIM * EE / 4));
    k_split<<<(int)(H_DIM * EE / 4 + 255) / 256, 256, 0, s1>>>((const float4*)Wq, (uint2*)Wqh, (uint2*)Wql, (int)(H_DIM * EE / 4));
    k_usum1<<<dim3(4, 32), 256, 0, s1>>>(x);
    k_usum2<<<4, 256, 0, s1>>>();
    k_qkbar<<<dim3(E_DIM, H_DIM, 2), 256, 0, s1>>>(Wq, Wk);
    k_trans_split<<<dim3(32, 32, H_DIM), tb, 0, s1>>>(Wv, WvTh, WvTl, E_DIM, E_DIM, EE, EE);
    k_split<<<(int)(H_DIM * EE / 4 + 255) / 256, 256, 0, s1>>>((const float4*)Wz, (uint2*)Wzh, (uint2*)Wzl, (int)(H_DIM * EE / 4));
    k_split<<<(int)(EE / 4 + 255) / 256, 256, 0, s1>>>((const float4*)Wf, (uint2*)Wfh, (uint2*)Wfl, (int)(EE / 4));
    k_split<<<(S_DIM * E_DIM / 4 + 255) / 256, 256, 0, s1>>>((const float4*)x, (uint2*)xh, (uint2*)xl, S_DIM * E_DIM / 4);
    cudaEventRecord(evPrep, s1);   // recorded NOW, waited later by s0

    // ======== main stream: critical path through softmax ========
    k_trans_split<<<dim3(E_DIM / 32, S_DIM / 32, 1), tb, 0, s0>>>(x, xTh, xTl, S_DIM, E_DIM, 0, 0);
    // G = x^T x (split-K4)
    { GemmP p{xTh, xTl, 1024, S_DIM, xTh, xTl, 1024, S_DIM,
              dG4, 0, 0, EE, E_DIM, nullptr, 1024};
      k_gemm<<<dim3(8, 8, 4), 256, SMEMB, s0>>>(p); }
    k_reduce_split<<<(int)(EE / 256), 256, 0, s0>>>(dG4, 4, (int)EE, Gh, Gl);
    // T_h = Wk_h @ G   (needs Wk split + qkbar -> wait on evPrep)
    cudaStreamWaitEvent(s0, evPrep, 0);
    { GemmP p{Wkh, Wkl, EE, E_DIM, Gh, Gl, 0, E_DIM,
              0, Th, Tl, EE, E_DIM, nullptr, E_DIM};
      k_gemm<<<dim3(8, 8, H_DIM), 256, SMEMB, s0>>>(p); }
    // scores_h = T_h @ Wq_h^T
    { GemmP p{Th, Tl, EE, E_DIM, Wqh, Wql, EE, E_DIM,
              dA, 0, 0, EE, E_DIM, nullptr, E_DIM};
      k_gemm<<<dim3(8, 8, H_DIM), 256, SMEMB, s0>>>(p); }
    // bias fixup + softmax
    k_softfix<<<H_DIM * E_DIM, 256, 0, s0>>>(bq, bk);
    cudaEventRecord(evSoft, s0);   // recorded BEFORE side-stream wait below

    // ======== side stream phase 2: rvec/cvec (needs softmaxed A) ========
    cudaStreamWaitEvent(s1, evSoft, 0);
    k_rvec1<<<dim3(4, H_DIM, 8), 256, 0, s1>>>(bv);
    k_rvec2<<<HE_DIM / 256, 256, 0, s1>>>();
    k_cvec<<<E_DIM, 256, 0, s1>>>(Wz, bz);
    cudaEventRecord(evC, s1);      // recorded BEFORE s0 waits on it

    // ======== main stream: remainder ========
    // A^T
    k_trans_split<<<dim3(32, 32, H_DIM), tb, 0, s0>>>(dA, ATh, ATl, E_DIM, E_DIM, EE, EE);
    // M_h = Wv_h^T @ A_h
    { GemmP p{WvTh, WvTl, EE, E_DIM, ATh, ATl, EE, E_DIM,
              0, Mh, Ml, EE, E_DIM, nullptr, E_DIM};
      k_gemm<<<dim3(8, 8, H_DIM), 256, SMEMB, s0>>>(p); }
    // PT8_h = Wz_h @ M_h
    { GemmP p{Wzh, Wzl, E_DIM, HE_DIM, Mh, Ml, EE, E_DIM,
              dPT8, 0, 0, EE, E_DIM, nullptr, E_DIM};
      k_gemm<<<dim3(8, 8, H_DIM), 256, SMEMB, s0>>>(p); }
    k_reduce_split<<<(int)(EE / 256), 256, 0, s0>>>(dPT8, 8, (int)EE, PTh, PTl);
    // O = x @ P + c   (needs x split + cvec)
    cudaStreamWaitEvent(s0, evC, 0);
    { GemmP p{xh, xl, 0, E_DIM, PTh, PTl, 0, E_DIM,
              dO, 0, 0, 0, E_DIM, dc, E_DIM};
      k_gemm<<<dim3(8, 32, 1), 256, SMEMB, s0>>>(p); }
    k_ln1<<<S_DIM, 256, 0, s0>>>(x, g1, b1);
    // FN = LN1 @ Wf^T + bf
    { GemmP p{L1h, L1l, 0, E_DIM, Wfh, Wfl, 0, E_DIM,
              dFN, 0, 0, 0, E_DIM, bf, E_DIM};
      k_gemm<<<dim3(8, 32, 1), 256, SMEMB, s0>>>(p); }
    k_ln2<<<S_DIM, 256, 0, s0>>>(g2, b2, out);
}

// round 7
// speedup vs baseline: 10.2797x; 1.0049x over previous
#include <cuda_runtime.h>
#include <cuda_bf16.h>
#include <cstdint>

#define S_DIM 4096
#define E_DIM 1024
#define H_DIM 8
#define HE_DIM 8192
typedef __nv_bfloat16 bf16;

// ---------------- fp32 scratch ----------------------------------------------
__device__ float g_A  [(size_t)H_DIM * E_DIM * E_DIM];  // scaled+biased logits 32MB
__device__ float g_G4 [(size_t)4 * E_DIM * E_DIM];
__device__ float g_PT8[(size_t)H_DIM * E_DIM * E_DIM];
__device__ float g_O  [(size_t)S_DIM * E_DIM];
__device__ float g_LN1[(size_t)S_DIM * E_DIM];
__device__ float g_FN [(size_t)S_DIM * E_DIM];
__device__ float g_u32p[32 * E_DIM];
__device__ float g_u  [E_DIM];
__device__ float g_qbar[H_DIM * E_DIM];   // holds qbar + 4096*bq (folded)
__device__ float g_kbar[H_DIM * E_DIM];
__device__ float g_rowm[H_DIM * E_DIM];   // per-row max of logits
__device__ float g_rowi[H_DIM * E_DIM];   // per-row 1/sum(exp)
__device__ float g_r  [H_DIM * E_DIM];
__device__ float g_c  [E_DIM];

// ---------------- bf16 hi/lo operand buffers ---------------------------------
__device__ bf16 b_xh [(size_t)S_DIM * E_DIM],  b_xl [(size_t)S_DIM * E_DIM];
__device__ bf16 b_xTh[(size_t)E_DIM * S_DIM],  b_xTl[(size_t)E_DIM * S_DIM];
__device__ bf16 b_Gh [(size_t)E_DIM * E_DIM],  b_Gl [(size_t)E_DIM * E_DIM];
__device__ bf16 b_Wkh[(size_t)H_DIM * E_DIM * E_DIM], b_Wkl[(size_t)H_DIM * E_DIM * E_DIM];
__device__ bf16 b_Wqh[(size_t)H_DIM * E_DIM * E_DIM], b_Wql[(size_t)H_DIM * E_DIM * E_DIM];
__device__ bf16 b_Th [(size_t)H_DIM * E_DIM * E_DIM], b_Tl [(size_t)H_DIM * E_DIM * E_DIM];
__device__ bf16 b_ATh[(size_t)H_DIM * E_DIM * E_DIM], b_ATl[(size_t)H_DIM * E_DIM * E_DIM];
__device__ bf16 b_WvTh[(size_t)H_DIM * E_DIM * E_DIM], b_WvTl[(size_t)H_DIM * E_DIM * E_DIM];
__device__ bf16 b_Mh [(size_t)H_DIM * E_DIM * E_DIM], b_Ml [(size_t)H_DIM * E_DIM * E_DIM];
__device__ bf16 b_Wzh[(size_t)H_DIM * E_DIM * E_DIM], b_Wzl[(size_t)H_DIM * E_DIM * E_DIM];
__device__ bf16 b_PTh[(size_t)E_DIM * E_DIM],  b_PTl[(size_t)E_DIM * E_DIM];
__device__ bf16 b_L1h[(size_t)S_DIM * E_DIM],  b_L1l[(size_t)S_DIM * E_DIM];
__device__ bf16 b_Wfh[(size_t)E_DIM * E_DIM],  b_Wfl[(size_t)E_DIM * E_DIM];

// ---------------- helpers ----------------------------------------------------
static __device__ __forceinline__ uint32_t s2u(const void* p) {
    uint32_t a;
    asm("{ .reg .u64 t; cvta.to.shared.u64 t, %1; cvt.u32.u64 %0, t; }"
        : "=r"(a) : "l"(p));
    return a;
}
static __device__ __forceinline__ uint32_t pack_bf(float a, float b) {
    uint32_t r;
    asm("cvt.rn.bf16x2.f32 %0, %1, %2;" : "=r"(r) : "f"(b), "f"(a));
    return r;
}
static __device__ __forceinline__ void ldsm4(uint32_t* r, uint32_t addr) {
    asm volatile("ldmatrix.sync.aligned.m8n8.x4.shared.b16 {%0,%1,%2,%3}, [%4];"
                 : "=r"(r[0]), "=r"(r[1]), "=r"(r[2]), "=r"(r[3]) : "r"(addr));
}
static __device__ __forceinline__ void mma16816(float* d, const uint32_t* a,
                                                const uint32_t* b) {
    asm volatile(
        "mma.sync.aligned.m16n8k16.row.col.f32.bf16.bf16.f32 "
        "{%0,%1,%2,%3},{%4,%5,%6,%7},{%8,%9},{%0,%1,%2,%3};"
        : "+f"(d[0]), "+f"(d[1]), "+f"(d[2]), "+f"(d[3])
        : "r"(a[0]), "r"(a[1]), "r"(a[2]), "r"(a[3]), "r"(b[0]), "r"(b[1]));
}
static __device__ __forceinline__ void cp16(uint32_t dst, const void* src) {
    asm volatile("cp.async.cg.shared.global [%0], [%1], 16;"
                 :: "r"(dst), "l"(src));
}

// ============================================================================
// bf16 hi/lo cp.async GEMM (NT): C = (A.B^T + eA⊗eC + eB⊗eD)*alpha + bn
// CTA 128x128, BK=32, 128 threads (4 warps 2x2, warp tile 64x64), 3 stages.
// ============================================================================
#define STAGEB 32768
#define SMEMB  (3 * STAGEB)

struct GemmP {
    const bf16 *Ah, *Al; long long As; int lda;
    const bf16 *Bh, *Bl; long long Bs; int ldb;
    float* Cf; bf16 *Ch, *Cl; long long Cs; int ldc;
    const float* bn;
    const float *eA, *eB, *eC, *eD; int eS;   // rank-1 epilogue (per z)
    float alpha;
    int K;
};

static __device__ __forceinline__ void issue_stage(
    uint32_t sbase, int slot,
    const bf16* __restrict__ Ah, const bf16* __restrict__ Al, int lda,
    const bf16* __restrict__ Bh, const bf16* __restrict__ Bl, int ldb,
    int k0, int tid) {
    uint32_t st = sbase + (uint32_t)slot * STAGEB;
#pragma unroll
    for (int i = 0; i < 16; i++) {
        int idx = tid + i * 128;              // 0..2047
        int half = idx >> 10;                 // 0 = A, 1 = B
        int r = (idx >> 3) & 127;
        int c = idx & 7;                      // chunk: 0-3 hi, 4-7 lo
        const bf16* base;
        int ld;
        if (half == 0) { base = (c < 4) ? Ah : Al; ld = lda; }
        else           { base = (c < 4) ? Bh : Bl; ld = ldb; }
        const char* src = (const char*)(base + (size_t)r * ld + k0) + (c & 3) * 16;
        uint32_t dst = st + (uint32_t)half * 16384u + (uint32_t)r * 128u
                     + (uint32_t)((c ^ (r & 7)) << 4);
        cp16(dst, src);
    }
}

__global__ __launch_bounds__(128, 2) void k_gemm(GemmP p) {
    extern __shared__ char smem[];
    const int tid = threadIdx.x;
    const int w = tid >> 5, l = tid & 31;
    const int wm = (w >> 1) * 64, wn = (w & 1) * 64;
    const int m0 = blockIdx.y * 128, n0 = blockIdx.x * 128;
    const int z = blockIdx.z;
    const uint32_t s0 = s2u(smem);

    const bf16* Abh = p.Ah + (size_t)z * p.As + (size_t)m0 * p.lda;
    const bf16* Abl = p.Al + (size_t)z * p.As + (size_t)m0 * p.lda;
    const bf16* Bbh = p.Bh + (size_t)z * p.Bs + (size_t)n0 * p.ldb;
    const bf16* Bbl = p.Bl + (size_t)z * p.Bs + (size_t)n0 * p.ldb;

    const uint32_t axor = (uint32_t)(l & 7);
    const uint32_t arow = (uint32_t)(wm + (l & 15));
    const uint32_t asel = (uint32_t)(l >> 4);
    const uint32_t brow = (uint32_t)(wn + (l & 7) + ((l >> 4) & 1) * 8);
    const uint32_t bsel = (uint32_t)((l >> 3) & 1);

    float acc[4][8][4];
#pragma unroll
    for (int t = 0; t < 4; t++)
#pragma unroll
        for (int j = 0; j < 8; j++)
#pragma unroll
            for (int r = 0; r < 4; r++) acc[t][j][r] = 0.f;

    const int NC = p.K >> 5;
    issue_stage(s0, 0, Abh, Abl, p.lda, Bbh, Bbl, p.ldb, 0, tid);
    asm volatile("cp.async.commit_group;" ::: "memory");
    issue_stage(s0, 1, Abh, Abl, p.lda, Bbh, Bbl, p.ldb, 32, tid);
    asm volatile("cp.async.commit_group;" ::: "memory");

    for (int c = 0; c < NC; c++) {
        asm volatile("cp.async.wait_group 1;" ::: "memory");
        __syncthreads();
        if (c + 2 < NC)
            issue_stage(s0, (c + 2) % 3, Abh, Abl, p.lda, Bbh, Bbl, p.ldb,
                        (c + 2) * 32, tid);
        asm volatile("cp.async.commit_group;" ::: "memory");

        uint32_t st = s0 + (uint32_t)(c % 3) * STAGEB;
#pragma unroll
        for (int ks = 0; ks < 2; ks++) {
            uint32_t bh[4][4], bl[4][4];
#pragma unroll
            for (int jp = 0; jp < 4; jp++) {
                uint32_t ba = st + 16384u + (brow + jp * 16u) * 128u
                            + (((2u * ks + bsel) ^ axor) << 4);
                ldsm4(bh[jp], ba);
                ldsm4(bl[jp], ba ^ 0x40u);
            }
#pragma unroll
            for (int t = 0; t < 4; t++) {
                uint32_t ah[4], al[4];
                uint32_t aa = st + (arow + t * 16u) * 128u
                            + (((2u * ks + asel) ^ axor) << 4);
                ldsm4(ah, aa);
                ldsm4(al, aa ^ 0x40u);
#pragma unroll
                for (int j = 0; j < 8; j++) {
                    uint32_t b0h[2] = { bh[j >> 1][(j & 1) * 2], bh[j >> 1][(j & 1) * 2 + 1] };
                    uint32_t b0l[2] = { bl[j >> 1][(j & 1) * 2], bl[j >> 1][(j & 1) * 2 + 1] };
                    mma16816(acc[t][j], ah, b0h);
                    mma16816(acc[t][j], ah, b0l);
                    mma16816(acc[t][j], al, b0h);
                }
            }
        }
    }

    float* Cf = p.Cf ? p.Cf + (size_t)z * p.Cs : (float*)0;
    bf16* Ch = p.Ch ? p.Ch + (size_t)z * p.Cs : (bf16*)0;
    bf16* Cl = p.Cl ? p.Cl + (size_t)z * p.Cs : (bf16*)0;
    const float* bn = p.bn;
    const float* eA = p.eA ? p.eA + (size_t)z * p.eS : (const float*)0;
    const float* eB = p.eB ? p.eB + (size_t)z * p.eS : (const float*)0;
    const float* eC = p.eC ? p.eC + (size_t)z * p.eS : (const float*)0;
    const float* eD = p.eD ? p.eD + (size_t)z * p.eS : (const float*)0;
    const float alpha = p.alpha;
#pragma unroll
    for (int t = 0; t < 4; t++) {
        int m = m0 + wm + t * 16 + (l >> 2);
#pragma unroll
        for (int j = 0; j < 8; j++) {
            int n = n0 + wn + j * 8 + (l & 3) * 2;
#pragma unroll
            for (int h2 = 0; h2 < 2; h2++) {
                float v0 = acc[t][j][h2 * 2], v1 = acc[t][j][h2 * 2 + 1];
                int mr = m + h2 * 8;
                if (eA) {
                    float a = eA[mr], b = eB[mr];
                    v0 += a * eC[n]     + b * eD[n];
                    v1 += a * eC[n + 1] + b * eD[n + 1];
                }
                v0 *= alpha; v1 *= alpha;
                if (bn) { v0 += bn[n]; v1 += bn[n + 1]; }
                if (Cf) *(float2*)(Cf + (size_t)mr * p.ldc + n) = make_float2(v0, v1);
                if (Ch) {
                    uint32_t hh = pack_bf(v0, v1);
                    *(uint32_t*)((char*)Ch + ((size_t)mr * p.ldc + n) * 2) = hh;
                    float l0 = v0 - __uint_as_float(hh << 16);
                    float l1 = v1 - __uint_as_float(hh & 0xFFFF0000u);
                    *(uint32_t*)((char*)Cl + ((size_t)mr * p.ldc + n) * 2) = pack_bf(l0, l1);
                }
            }
        }
    }
}

// ---------------- reductions -------------------------------------------------
static __device__ __forceinline__ float blockReduceSum256(float v) {
    __shared__ float sb[8];
#pragma unroll
    for (int o = 16; o > 0; o >>= 1) v += __shfl_xor_sync(0xffffffffu, v, o);
    __syncthreads();
    if ((threadIdx.x & 31) == 0) sb[threadIdx.x >> 5] = v;
    __syncthreads();
    float r = sb[0];
#pragma unroll
    for (int i = 1; i < 8; i++) r += sb[i];
    return r;
}
static __device__ __forceinline__ float blockReduceMax256(float v) {
    __shared__ float sb[8];
#pragma unroll
    for (int o = 16; o > 0; o >>= 1) v = fmaxf(v, __shfl_xor_sync(0xffffffffu, v, o));
    __syncthreads();
    if ((threadIdx.x & 31) == 0) sb[threadIdx.x >> 5] = v;
    __syncthreads();
    float r = sb[0];
#pragma unroll
    for (int i = 1; i < 8; i++) r = fmaxf(r, sb[i]);
    return r;
}

// ---------------- conversion / transpose kernels ------------------------------
__global__ void k_split(const float4* __restrict__ src, uint2* __restrict__ hi,
                        uint2* __restrict__ lo, int n4) {
    int i = blockIdx.x * 256 + threadIdx.x;
    if (i >= n4) return;
    float4 v = src[i];
    uint32_t h0 = pack_bf(v.x, v.y), h1 = pack_bf(v.z, v.w);
    float lx = v.x - __uint_as_float(h0 << 16);
    float ly = v.y - __uint_as_float(h0 & 0xFFFF0000u);
    float lz = v.z - __uint_as_float(h1 << 16);
    float lw = v.w - __uint_as_float(h1 & 0xFFFF0000u);
    hi[i] = make_uint2(h0, h1);
    lo[i] = make_uint2(pack_bf(lx, ly), pack_bf(lz, lw));
}

__global__ void k_trans_split(const float* __restrict__ src,
                              bf16* __restrict__ hi, bf16* __restrict__ lo,
                              int R, int C, long long ss, long long ds) {
    __shared__ float t[32][33];
    src += (size_t)blockIdx.z * ss;
    hi += (size_t)blockIdx.z * ds;
    lo += (size_t)blockIdx.z * ds;
    int c0 = blockIdx.x * 32, r0 = blockIdx.y * 32;
#pragma unroll
    for (int i = 0; i < 32; i += 8)
        t[threadIdx.y + i][threadIdx.x] =
            src[(size_t)(r0 + threadIdx.y + i) * C + c0 + threadIdx.x];
    __syncthreads();
#pragma unroll
    for (int i = 0; i < 32; i += 8) {
        float v = t[threadIdx.x][threadIdx.y + i];
        bf16 h = __float2bfloat16_rn(v);
        size_t o = (size_t)(c0 + threadIdx.y + i) * R + r0 + threadIdx.x;
        hi[o] = h;
        lo[o] = __float2bfloat16_rn(v - __bfloat162float(h));
    }
}

// row max + 1/sum(exp) of logits
__global__ __launch_bounds__(256, 4) void k_rowstat() {
    int row = blockIdx.x;
    const float* p = g_A + (size_t)row * E_DIM;
    int tid = threadIdx.x;
    float v[4];
    float m = -1e30f;
#pragma unroll
    for (int i = 0; i < 4; i++) { v[i] = p[tid + i * 256]; m = fmaxf(m, v[i]); }
    m = blockReduceMax256(m);
    float s = 0;
#pragma unroll
    for (int i = 0; i < 4; i++) s += __expf(v[i] - m);
    s = blockReduceSum256(s);
    if (tid == 0) { g_rowm[row] = m; g_rowi[row] = 1.0f / s; }
}

// AT[f,e] = exp(A[e,f]-m[e])*inv[e], hi/lo split, transposed write
__global__ void k_transexp(bf16* __restrict__ hi, bf16* __restrict__ lo) {
    __shared__ float t[32][33];
    int h = blockIdx.z;
    const float* src = g_A + (size_t)h * E_DIM * E_DIM;
    bf16* hih = hi + (size_t)h * E_DIM * E_DIM;
    bf16* loh = lo + (size_t)h * E_DIM * E_DIM;
    int f0 = blockIdx.x * 32, e0 = blockIdx.y * 32;
#pragma unroll
    for (int i = 0; i < 32; i += 8) {
        int e = e0 + threadIdx.y + i;
        float m = g_rowm[h * E_DIM + e], inv = g_rowi[h * E_DIM + e];
        float v = src[(size_t)e * E_DIM + f0 + threadIdx.x];
        t[threadIdx.y + i][threadIdx.x] = __expf(v - m) * inv;
    }
    __syncthreads();
#pragma unroll
    for (int i = 0; i < 32; i += 8) {
        float v = t[threadIdx.x][threadIdx.y + i];
        bf16 hh = __float2bfloat16_rn(v);
        size_t o = (size_t)(f0 + threadIdx.y + i) * E_DIM + e0 + threadIdx.x;
        hih[o] = hh;
        loh[o] = __float2bfloat16_rn(v - __bfloat162float(hh));
    }
}

__global__ void k_reduce_split(const float* __restrict__ src, int Z, int total,
                               bf16* __restrict__ hi, bf16* __restrict__ lo) {
    int i = blockIdx.x * 256 + threadIdx.x;
    if (i >= total) return;
    float s = 0;
    for (int zz = 0; zz < Z; zz++) s += src[(size_t)zz * total + i];
    bf16 h = __float2bfloat16_rn(s);
    hi[i] = h;
    lo[i] = __float2bfloat16_rn(s - __bfloat162float(h));
}

// ---------------- small algebra kernels ---------------------------------------
__global__ void k_usum1(const float* __restrict__ x) {
    int e = blockIdx.x * 256 + threadIdx.x;
    int zc = blockIdx.y;
    float s = 0;
    for (int si = zc * 128; si < zc * 128 + 128; si++) s += x[(size_t)si * E_DIM + e];
    g_u32p[zc * E_DIM + e] = s;
}
__global__ void k_usum2() {
    int e = blockIdx.x * 256 + threadIdx.x;
    float s = 0;
    for (int zc = 0; zc < 32; zc++) s += g_u32p[zc * E_DIM + e];
    g_u[e] = s;
}
// qbar' = u.Wq_row + 4096*bq ; kbar = u.Wk_row
__global__ void k_qkbar(const float* __restrict__ Wq, const float* __restrict__ Wk,
                        const float* __restrict__ bq) {
    int f = blockIdx.x, h = blockIdx.y;
    const float* Wrow = (blockIdx.z == 0 ? Wq : Wk) + ((size_t)h * E_DIM + f) * E_DIM;
    float s = 0;
    for (int i = threadIdx.x; i < E_DIM; i += 256) s += g_u[i] * Wrow[i];
    s = blockReduceSum256(s);
    if (threadIdx.x == 0) {
        if (blockIdx.z == 0) g_qbar[h * E_DIM + f] = s + 4096.0f * bq[h * E_DIM + f];
        else                 g_kbar[h * E_DIM + f] = s;
    }
}

// r[h,f] = sum_e softA[h,e,f]*bv[h,e] via AT rows (hi+lo)
__global__ void k_rvec(const bf16* __restrict__ ATh, const bf16* __restrict__ ATl,
                       const float* __restrict__ bv) {
    int f = blockIdx.x, h = blockIdx.y;
    const bf16* ph = ATh + ((size_t)h * E_DIM + f) * E_DIM;
    const bf16* pl = ATl + ((size_t)h * E_DIM + f) * E_DIM;
    const float* bvh = bv + h * E_DIM;
    float s = 0;
    for (int e = threadIdx.x; e < E_DIM; e += 256)
        s += (__bfloat162float(ph[e]) + __bfloat162float(pl[e])) * bvh[e];
    s = blockReduceSum256(s);
    if (threadIdx.x == 0) g_r[h * E_DIM + f] = s;
}
__global__ void k_cvec(const float* __restrict__ Wz, const float* __restrict__ bz) {
    int o = blockIdx.x;
    const float* wrow = Wz + (size_t)o * HE_DIM;
    float s = 0;
    for (int i = threadIdx.x; i < HE_DIM; i += 256) s += g_r[i] * wrow[i];
    s = blockReduceSum256(s);
    if (threadIdx.x == 0) g_c[o] = bz[o] + s;
}

// LN1 = LN(O)*g1+b1 + x  (writes fp32 + bf16 hi/lo)
__global__ __launch_bounds__(256, 4)
void k_ln1(const float* __restrict__ x, const float* __restrict__ g,
           const float* __restrict__ b) {
    const size_t row = blockIdx.x;
    const int tid = threadIdx.x;
    const float* p = g_O + row * E_DIM;
    float v[4];
    float s = 0.f;
#pragma unroll
    for (int i = 0; i < 4; i++) { v[i] = p[tid + i * 256]; s += v[i]; }
    const float mean = blockReduceSum256(s) * (1.0f / E_DIM);
    float q = 0.f;
#pragma unroll
    for (int i = 0; i < 4; i++) { const float d = v[i] - mean; q += d * d; }
    const float var = blockReduceSum256(q) * (1.0f / E_DIM);
    const float rstd = rsqrtf(var + 1e-5f);
#pragma unroll
    for (int i = 0; i < 4; i++) {
        const int idx = tid + i * 256;
        float o = (v[i] - mean) * rstd * g[idx] + b[idx] + x[row * E_DIM + idx];
        g_LN1[row * E_DIM + idx] = o;
        bf16 h = __float2bfloat16_rn(o);
        b_L1h[row * E_DIM + idx] = h;
        b_L1l[row * E_DIM + idx] = __float2bfloat16_rn(o - __bfloat162float(h));
    }
}

__global__ __launch_bounds__(256, 4)
void k_ln2(const float* __restrict__ g, const float* __restrict__ b,
           float* __restrict__ out) {
    const size_t row = blockIdx.x;
    const int tid = threadIdx.x;
    const float* p = g_FN + row * E_DIM;
    float v[4];
    float s = 0.f;
#pragma unroll
    for (int i = 0; i < 4; i++) { v[i] = p[tid + i * 256]; s += v[i]; }
    const float mean = blockReduceSum256(s) * (1.0f / E_DIM);
    float q = 0.f;
#pragma unroll
    for (int i = 0; i < 4; i++) { const float d = v[i] - mean; q += d * d; }
    const float var = blockReduceSum256(q) * (1.0f / E_DIM);
    const float rstd = rsqrtf(var + 1e-5f);
#pragma unroll
    for (int i = 0; i < 4; i++) {
        const int idx = tid + i * 256;
        out[row * E_DIM + idx] =
            (v[i] - mean) * rstd * g[idx] + b[idx] + g_LN1[row * E_DIM + idx];
    }
}

// ============================================================================
// Launch — fork/join two-stream graph (record ALWAYS precedes wait)
// ============================================================================
#define SYM(v, s) cudaGetSymbolAddress((void**)&v, s)

static cudaStream_t g_s1;
static cudaEvent_t evFork, evPrep, evAT, evC;
static bool g_init = false;

extern "C" void kernel_launch(void* const* d_in, const int* in_sizes, int n_in,
                              void* d_out, int out_size) {
    (void)in_sizes; (void)n_in; (void)out_size;
    const float* x  = (const float*)d_in[0];
    const float* Wq = (const float*)d_in[1];
    const float* bq = (const float*)d_in[2];
    const float* Wk = (const float*)d_in[3];
    const float* bk = (const float*)d_in[4];
    const float* Wv = (const float*)d_in[5];
    const float* bv = (const float*)d_in[6];
    const float* Wz = (const float*)d_in[7];
    const float* bz = (const float*)d_in[8];
    const float* g1 = (const float*)d_in[9];
    const float* b1 = (const float*)d_in[10];
    const float* Wf = (const float*)d_in[11];
    const float* bf = (const float*)d_in[12];
    const float* g2 = (const float*)d_in[13];
    const float* b2 = (const float*)d_in[14];
    float* out = (float*)d_out;

    if (!g_init) {
        cudaFuncSetAttribute(k_gemm, cudaFuncAttributeMaxDynamicSharedMemorySize, SMEMB);
        cudaStreamCreateWithFlags(&g_s1, cudaStreamNonBlocking);
        cudaEventCreateWithFlags(&evFork, cudaEventDisableTiming);
        cudaEventCreateWithFlags(&evPrep, cudaEventDisableTiming);
        cudaEventCreateWithFlags(&evAT,   cudaEventDisableTiming);
        cudaEventCreateWithFlags(&evC,    cudaEventDisableTiming);
        g_init = true;
    }

    float *dA, *dG4, *dPT8, *dO, *dc, *dFN, *dqbar, *dkbar;
    SYM(dA, g_A); SYM(dG4, g_G4); SYM(dPT8, g_PT8); SYM(dO, g_O); SYM(dc, g_c);
    SYM(dFN, g_FN); SYM(dqbar, g_qbar); SYM(dkbar, g_kbar);
    bf16 *xh, *xl, *xTh, *xTl, *Gh, *Gl, *Wkh, *Wkl, *Wqh, *Wql, *Th, *Tl;
    bf16 *ATh, *ATl, *WvTh, *WvTl, *Mh, *Ml, *Wzh, *Wzl, *PTh, *PTl;
    bf16 *L1h, *L1l, *Wfh, *Wfl;
    SYM(xh, b_xh); SYM(xl, b_xl); SYM(xTh, b_xTh); SYM(xTl, b_xTl);
    SYM(Gh, b_Gh); SYM(Gl, b_Gl); SYM(Wkh, b_Wkh); SYM(Wkl, b_Wkl);
    SYM(Wqh, b_Wqh); SYM(Wql, b_Wql); SYM(Th, b_Th); SYM(Tl, b_Tl);
    SYM(ATh, b_ATh); SYM(ATl, b_ATl); SYM(WvTh, b_WvTh); SYM(WvTl, b_WvTl);
    SYM(Mh, b_Mh); SYM(Ml, b_Ml); SYM(Wzh, b_Wzh); SYM(Wzl, b_Wzl);
    SYM(PTh, b_PTh); SYM(PTl, b_PTl); SYM(L1h, b_L1h); SYM(L1l, b_L1l);
    SYM(Wfh, b_Wfh); SYM(Wfl, b_Wfl);

    const long long EE = (long long)E_DIM * E_DIM;
    dim3 tb(32, 8);
    cudaStream_t s0 = 0, s1 = g_s1;

    cudaEventRecord(evFork, s0);
    cudaStreamWaitEvent(s1, evFork, 0);

    // ======== side stream phase 1: input-only prep ========
    k_split<<<(int)(H_DIM * EE / 4 + 255) / 256, 256, 0, s1>>>((const float4*)Wk, (uint2*)Wkh, (uint2*)Wkl, (int)(H_DIM * EE / 4));
    k_split<<<(int)(H_DIM * EE / 4 + 255) / 256, 256, 0, s1>>>((const float4*)Wq, (uint2*)Wqh, (uint2*)Wql, (int)(H_DIM * EE / 4));
    k_usum1<<<dim3(4, 32), 256, 0, s1>>>(x);
    k_usum2<<<4, 256, 0, s1>>>();
    k_qkbar<<<dim3(E_DIM, H_DIM, 2), 256, 0, s1>>>(Wq, Wk, bq);
    k_trans_split<<<dim3(32, 32, H_DIM), tb, 0, s1>>>(Wv, WvTh, WvTl, E_DIM, E_DIM, EE, EE);
    k_split<<<(int)(H_DIM * EE / 4 + 255) / 256, 256, 0, s1>>>((const float4*)Wz, (uint2*)Wzh, (uint2*)Wzl, (int)(H_DIM * EE / 4));
    k_split<<<(int)(EE / 4 + 255) / 256, 256, 0, s1>>>((const float4*)Wf, (uint2*)Wfh, (uint2*)Wfl, (int)(EE / 4));
    k_split<<<(S_DIM * E_DIM / 4 + 255) / 256, 256, 0, s1>>>((const float4*)x, (uint2*)xh, (uint2*)xl, S_DIM * E_DIM / 4);
    cudaEventRecord(evPrep, s1);

    // ======== main stream: critical path through AT ========
    k_trans_split<<<dim3(E_DIM / 32, S_DIM / 32, 1), tb, 0, s0>>>(x, xTh, xTl, S_DIM, E_DIM, 0, 0);
    // G = x^T x (split-K4)
    { GemmP p{xTh, xTl, 1024, S_DIM, xTh, xTl, 1024, S_DIM,
              dG4, 0, 0, EE, E_DIM, nullptr,
              nullptr, nullptr, nullptr, nullptr, 0, 1.0f, 1024};
      k_gemm<<<dim3(8, 8, 4), 128, SMEMB, s0>>>(p); }
    k_reduce_split<<<(int)(EE / 256), 256, 0, s0>>>(dG4, 4, (int)EE, Gh, Gl);
    // T_h = Wk_h @ G
    cudaStreamWaitEvent(s0, evPrep, 0);
    { GemmP p{Wkh, Wkl, EE, E_DIM, Gh, Gl, 0, E_DIM,
              0, Th, Tl, EE, E_DIM, nullptr,
              nullptr, nullptr, nullptr, nullptr, 0, 1.0f, E_DIM};
      k_gemm<<<dim3(8, 8, H_DIM), 128, SMEMB, s0>>>(p); }
    // logits_h = (T_h @ Wq_h^T + bk⊗qbar' + kbar⊗bq) / 32
    { GemmP p{Th, Tl, EE, E_DIM, Wqh, Wql, EE, E_DIM,
              dA, 0, 0, EE, E_DIM, nullptr,
              bk, dkbar, dqbar, bq, E_DIM, 0.03125f, E_DIM};
      k_gemm<<<dim3(8, 8, H_DIM), 128, SMEMB, s0>>>(p); }
    // softmax stats + transposed exp
    k_rowstat<<<H_DIM * E_DIM, 256, 0, s0>>>();
    k_transexp<<<dim3(32, 32, H_DIM), tb, 0, s0>>>(ATh, ATl);
    cudaEventRecord(evAT, s0);

    // ======== side stream phase 2: rvec/cvec from AT ========
    cudaStreamWaitEvent(s1, evAT, 0);
    k_rvec<<<dim3(E_DIM, H_DIM), 256, 0, s1>>>(ATh, ATl, bv);
    k_cvec<<<E_DIM, 256, 0, s1>>>(Wz, bz);
    cudaEventRecord(evC, s1);

    // ======== main stream: remainder ========
    // M_h = Wv_h^T @ A_h
    { GemmP p{WvTh, WvTl, EE, E_DIM, ATh, ATl, EE, E_DIM,
              0, Mh, Ml, EE, E_DIM, nullptr,
              nullptr, nullptr, nullptr, nullptr, 0, 1.0f, E_DIM};
      k_gemm<<<dim3(8, 8, H_DIM), 128, SMEMB, s0>>>(p); }
    // PT8_h = Wz_h @ M_h
    { GemmP p{Wzh, Wzl, E_DIM, HE_DIM, Mh, Ml, EE, E_DIM,
              dPT8, 0, 0, EE, E_DIM, nullptr,
              nullptr, nullptr, nullptr, nullptr, 0, 1.0f, E_DIM};
      k_gemm<<<dim3(8, 8, H_DIM), 128, SMEMB, s0>>>(p); }
    k_reduce_split<<<(int)(EE / 256), 256, 0, s0>>>(dPT8, 8, (int)EE, PTh, PTl);
    // O = x @ P + c
    cudaStreamWaitEvent(s0, evC, 0);
    { GemmP p{xh, xl, 0, E_DIM, PTh, PTl, 0, E_DIM,
              dO, 0, 0, 0, E_DIM, dc,
              nullptr, nullptr, nullptr, nullptr, 0, 1.0f, E_DIM};
      k_gemm<<<dim3(8, 32, 1), 128, SMEMB, s0>>>(p); }
    k_ln1<<<S_DIM, 256, 0, s0>>>(x, g1, b1);
    // FN = LN1 @ Wf^T + bf
    { GemmP p{L1h, L1l, 0, E_DIM, Wfh, Wfl, 0, E_DIM,
              dFN, 0, 0, 0, E_DIM, bf,
              nullptr, nullptr, nullptr, nullptr, 0, 1.0f, E_DIM};
      k_gemm<<<dim3(8, 32, 1), 128, SMEMB, s0>>>(p); }
    k_ln2<<<S_DIM, 256, 0, s0>>>(g2, b2, out);
}